// round 10
// baseline (speedup 1.0000x reference)
#include <cuda_runtime.h>
#include <cuda_bf16.h>
#include <math.h>
#include <stdint.h>

// Problem constants
#define BQ    8
#define CIN   256
#define COUT  256
#define NPTS  8192
#define LQ    (3 * NPTS)      // 24576 columns per (batch) GEMM
#define MTOT  (2 * COUT)      // 512 rows: [W_feat; W_dir]

// GEMM tiling
#define BM 128
#define BN 128
#define BK 64                 // 128 bytes per row per chunk
#define KEFF 768              // 3 split passes x 256
#define NKC  (KEFF / BK)      // 12 chunks
#define NSTAGE 3
#define LOOKAHEAD 2

// SMEM: rows of 128B data padded to 144B pitch
// bank stride 36 = 4 mod 32 -> conflict-free 8-lane phases (stores + ldmatrix)
#define ROWP 144
#define A_TILE_BYTES (BM * ROWP)                   // 18432
#define B_TILE_BYTES (BN * ROWP)                   // 18432
#define STAGE_BYTES (A_TILE_BYTES + B_TILE_BYTES)  // 36864
#define SMEM_TOTAL (NSTAGE * STAGE_BYTES)          // 110592 (x2 CTA = 216KB <= 227KB)

// ---------------------------------------------------------------------------
// Static device scratch (no runtime allocation)
// ---------------------------------------------------------------------------
__device__ float g_p[(size_t)BQ * COUT * LQ];   // 192 MiB
__device__ float g_d[(size_t)BQ * COUT * LQ];   // 192 MiB
__device__ __nv_bfloat16 g_xhi[(size_t)BQ * LQ * CIN];  // transposed [b, l, k]
__device__ __nv_bfloat16 g_xlo[(size_t)BQ * LQ * CIN];
__device__ __nv_bfloat16 g_whi[MTOT * CIN];
__device__ __nv_bfloat16 g_wlo[MTOT * CIN];
__device__ float g_sum[COUT];
__device__ float g_sumsq[COUT];
__device__ float g_bn_a[COUT];
__device__ float g_bn_b[COUT];

// ---------------------------------------------------------------------------
// PTX helpers (sm_80-era: valid for plain sm_103 target)
// ---------------------------------------------------------------------------
__device__ __forceinline__ uint32_t smem_u32(const void* p) {
    uint32_t a;
    asm("{ .reg .u64 t; cvta.to.shared.u64 t, %1; cvt.u32.u64 %0, t; }" : "=r"(a) : "l"(p));
    return a;
}

__device__ __forceinline__ void cp16(uint32_t dst, const void* src) {
    asm volatile("cp.async.cg.shared.global [%0], [%1], 16;" :: "r"(dst), "l"(src) : "memory");
}
#define CP_COMMIT() asm volatile("cp.async.commit_group;" ::: "memory")
#define CP_WAIT(n)  asm volatile("cp.async.wait_group %0;" :: "n"(n) : "memory")

__device__ __forceinline__ void ldsm4(uint32_t* r, uint32_t addr) {
    asm volatile("ldmatrix.sync.aligned.m8n8.x4.shared.b16 {%0,%1,%2,%3}, [%4];"
                 : "=r"(r[0]), "=r"(r[1]), "=r"(r[2]), "=r"(r[3]) : "r"(addr));
}

__device__ __forceinline__ void mma16816(float* c, const uint32_t* a,
                                         uint32_t b0, uint32_t b1) {
    asm volatile(
        "mma.sync.aligned.m16n8k16.row.col.f32.bf16.bf16.f32 "
        "{%0,%1,%2,%3}, {%4,%5,%6,%7}, {%8,%9}, {%0,%1,%2,%3};"
        : "+f"(c[0]), "+f"(c[1]), "+f"(c[2]), "+f"(c[3])
        : "r"(a[0]), "r"(a[1]), "r"(a[2]), "r"(a[3]), "r"(b0), "r"(b1));
}

// ---------------------------------------------------------------------------
// K_a: W -> concatenated bf16 hi/lo [512, 256]
// ---------------------------------------------------------------------------
__global__ void convert_w_kernel(const float* __restrict__ Wf, const float* __restrict__ Wd)
{
    int row = blockIdx.x;
    int col = threadIdx.x;
    float v = (row < COUT) ? Wf[row * CIN + col] : Wd[(row - COUT) * CIN + col];
    __nv_bfloat16 hi = __float2bfloat16(v);
    float r = v - __bfloat162float(hi);
    g_whi[row * CIN + col] = hi;
    g_wlo[row * CIN + col] = __float2bfloat16(r);
}

// ---------------------------------------------------------------------------
// K_b: x [b, k, l] fp32 -> Xt_hi/Xt_lo [b, l, k] bf16 (transpose + split)
// ---------------------------------------------------------------------------
__global__ __launch_bounds__(256)
void transpose_split_kernel(const float* __restrict__ x)
{
    __shared__ float s[32][33];
    const int b  = blockIdx.z;
    const int k0 = blockIdx.y * 32;
    const int l0 = blockIdx.x * 32;
    const int tx = threadIdx.x, ty = threadIdx.y;

    const float* xb = x + ((size_t)b * CIN + k0) * LQ + l0;
#pragma unroll
    for (int i = 0; i < 4; i++) {
        int k = ty + i * 8;
        s[k][tx] = xb[(size_t)k * LQ + tx];
    }
    __syncthreads();
#pragma unroll
    for (int i = 0; i < 4; i++) {
        int lr = ty + i * 8;
        float v = s[tx][lr];
        __nv_bfloat16 hi = __float2bfloat16(v);
        float r = v - __bfloat162float(hi);
        size_t off = ((size_t)b * LQ + l0 + lr) * CIN + k0 + tx;
        g_xhi[off] = hi;
        g_xlo[off] = __float2bfloat16(r);
    }
}

// ---------------------------------------------------------------------------
// K1: mma.sync bf16 GEMM  C[512, 24576] (3-pass split) per batch
// grid (4 m, 192 l, 8 b), 256 threads, 8 warps as 4(m) x 2(n), warp m32xn64
// BK=64 chunks, 3-stage cp.async pipeline, ONE barrier per 4 k16-steps
// ---------------------------------------------------------------------------
__global__ __launch_bounds__(256, 2)
void gemm_mma_kernel()
{
    extern __shared__ char smem[];            // NSTAGE * STAGE_BYTES
    const uint32_t su = smem_u32(smem);

    const int tid  = threadIdx.x;
    const int lane = tid & 31;
    const int w    = tid >> 5;
    const int wm   = w >> 1;                  // 0..3 -> 32 m rows each
    const int wn   = w & 1;                   // 0..1 -> 64 l cols each

    const int m0 = blockIdx.x * BM;           // 0,128,256,384 concat rows
    const int l0 = blockIdx.y * BN;
    const int b  = blockIdx.z;
    const size_t blbase = (size_t)b * LQ + l0;

    float acc[2][8][4];                       // 64 regs (warp m32 x n64)
#pragma unroll
    for (int i = 0; i < 2; i++)
#pragma unroll
        for (int j = 0; j < 8; j++)
#pragma unroll
            for (int q = 0; q < 4; q++) acc[i][j][q] = 0.f;

    // Per stage: A 128 rows x 8 chunks(16B) = 1024 segs, B same.
    // tid < 128: rows=tid,     ch = {0,2,4,6}
    // tid >=128: rows=tid-128, ch = {1,3,5,7}
    const int srow = tid & 127;
    const int cb   = tid >> 7;                // ch parity
    auto load_stage = [&](int st, int kc) {
        const int seg  = kc >> 2;             // 0,1,2  (4 chunks per 256-k pass)
        const int koff = (kc & 3) * BK;
        const __nv_bfloat16* Asrc = (seg < 2) ? g_whi : g_wlo;
        const __nv_bfloat16* Bsrc = (seg == 1) ? g_xlo : g_xhi;
        const uint32_t abase = su + st * STAGE_BYTES;
        const uint32_t bbase = abase + A_TILE_BYTES;
        const __nv_bfloat16* arow = Asrc + (size_t)(m0 + srow) * CIN + koff;
        const __nv_bfloat16* brow = Bsrc + (blbase + srow) * CIN + koff;
#pragma unroll
        for (int i = 0; i < 4; i++) {
            int ch = i * 2 + cb;
            cp16(abase + srow * ROWP + ch * 16, arow + ch * 8);
            cp16(bbase + srow * ROWP + ch * 16, brow + ch * 8);
        }
        CP_COMMIT();
    };

    // Prologue: fill LOOKAHEAD stages
    load_stage(0, 0);
    load_stage(1, 1);

    const int lrow  = lane & 15;
    const int lhalf = lane >> 4;

    int st = 0;
    for (int kc = 0; kc < NKC; kc++) {
        CP_WAIT(LOOKAHEAD - 1);                // chunk kc arrived (exact: 1 group/iter)
        __syncthreads();                       // all warps done with stage kc-1
        if (kc + LOOKAHEAD < NKC) {
            int nst = st + LOOKAHEAD; if (nst >= NSTAGE) nst -= NSTAGE;
            load_stage(nst, kc + LOOKAHEAD);
        } else {
            CP_COMMIT();                       // empty group keeps wait arithmetic exact
        }

        const uint32_t abase = su + st * STAGE_BYTES;
        const uint32_t bbase = abase + A_TILE_BYTES;
        const uint32_t arow0 = abase + (wm * 32 + lrow) * ROWP + lhalf * 16;
        const uint32_t brow0 = bbase + (wn * 64 + lrow) * ROWP + lhalf * 16;

#pragma unroll
        for (int kk = 0; kk < 4; kk++) {       // four k16 steps in BK=64
            uint32_t a[2][4], bf[4][4];
#pragma unroll
            for (int i = 0; i < 2; i++)
                ldsm4(a[i], arow0 + i * 16 * ROWP + kk * 32);
#pragma unroll
            for (int j = 0; j < 4; j++)
                ldsm4(bf[j], brow0 + j * 16 * ROWP + kk * 32);
#pragma unroll
            for (int i = 0; i < 2; i++)
#pragma unroll
                for (int j = 0; j < 4; j++) {
                    mma16816(acc[i][2 * j],     a[i], bf[j][0], bf[j][2]);
                    mma16816(acc[i][2 * j + 1], a[i], bf[j][1], bf[j][3]);
                }
        }
        st++; if (st >= NSTAGE) st -= NSTAGE;
    }

    // Epilogue: fragment -> g_p / g_d
    float* buf = (m0 < COUT) ? g_p : g_d;
#pragma unroll
    for (int i = 0; i < 2; i++) {
        int mrow0 = (m0 & (COUT - 1)) + wm * 32 + i * 16 + (lane >> 2);
#pragma unroll
        for (int j = 0; j < 8; j++) {
            int cg = l0 + wn * 64 + j * 8 + (lane & 3) * 2;
            float2 v0 = make_float2(acc[i][j][0], acc[i][j][1]);
            float2 v1 = make_float2(acc[i][j][2], acc[i][j][3]);
            *reinterpret_cast<float2*>(buf + ((size_t)b * COUT + mrow0) * LQ + cg)     = v0;
            *reinterpret_cast<float2*>(buf + ((size_t)b * COUT + mrow0 + 8) * LQ + cg) = v1;
        }
    }
}

// ---------------------------------------------------------------------------
// K0: zero stats accumulators
// ---------------------------------------------------------------------------
__global__ void zero_stats_kernel()
{
    int i = threadIdx.x;
    g_sum[i]   = 0.f;
    g_sumsq[i] = 0.f;
}

// ---------------------------------------------------------------------------
// K2: per-channel sum / sumsq of vector norms
// ---------------------------------------------------------------------------
__global__ __launch_bounds__(256)
void stats_kernel()
{
    const int o = blockIdx.x;
    const int b = blockIdx.y;
    const float* base = g_p + ((size_t)b * COUT + o) * LQ;

    float s = 0.f, s2 = 0.f;
    for (int n = threadIdx.x; n < NPTS; n += 256) {
        float px = base[n];
        float py = base[NPTS + n];
        float pz = base[2 * NPTS + n];
        float nrm = sqrtf(px * px + py * py + pz * pz);
        s  += nrm;
        s2 += nrm * nrm;
    }
#pragma unroll
    for (int off = 16; off > 0; off >>= 1) {
        s  += __shfl_down_sync(0xffffffffu, s,  off);
        s2 += __shfl_down_sync(0xffffffffu, s2, off);
    }
    __shared__ float shs[8], shs2[8];
    int wid = threadIdx.x >> 5;
    int lid = threadIdx.x & 31;
    if (lid == 0) { shs[wid] = s; shs2[wid] = s2; }
    __syncthreads();
    if (threadIdx.x == 0) {
        float ts = 0.f, ts2 = 0.f;
#pragma unroll
        for (int w = 0; w < 8; w++) { ts += shs[w]; ts2 += shs2[w]; }
        atomicAdd(&g_sum[o],   ts);
        atomicAdd(&g_sumsq[o], ts2);
    }
}

// ---------------------------------------------------------------------------
// K3: finalize BN affine per channel
// ---------------------------------------------------------------------------
__global__ void finalize_kernel(const float* __restrict__ gamma,
                                const float* __restrict__ beta)
{
    int o = threadIdx.x;
    const float inv = 1.0f / (float)(BQ * NPTS);
    float mean = g_sum[o] * inv;
    float var  = g_sumsq[o] * inv - mean * mean;
    float rstd = rsqrtf(var + 1e-5f);
    float a = rstd * gamma[o];
    g_bn_a[o] = a;
    g_bn_b[o] = beta[o] - mean * a;
}

// ---------------------------------------------------------------------------
// K4: BN rescale + VN LeakyReLU
// ---------------------------------------------------------------------------
__global__ __launch_bounds__(256)
void epilogue_kernel(float* __restrict__ out)
{
    const int n = blockIdx.x * 256 + threadIdx.x;
    const int o = blockIdx.y;
    const int b = blockIdx.z;
    const size_t base = ((size_t)b * COUT + o) * LQ + n;

    float px = g_p[base];
    float py = g_p[base + NPTS];
    float pz = g_p[base + 2 * NPTS];
    float dx = g_d[base];
    float dy = g_d[base + NPTS];
    float dz = g_d[base + 2 * NPTS];

    float nrm = sqrtf(px * px + py * py + pz * pz);
    float f = __ldg(&g_bn_a[o]) + __ldg(&g_bn_b[o]) / nrm;
    px *= f; py *= f; pz *= f;

    float dot = px * dx + py * dy + pz * dz;
    float dsq = dx * dx + dy * dy + dz * dz;
    if (dot < 0.f) {
        float c = 0.8f * dot / (dsq + 1e-6f);
        px -= c * dx; py -= c * dy; pz -= c * dz;
    }
    out[base]            = px;
    out[base + NPTS]     = py;
    out[base + 2 * NPTS] = pz;
}

// ---------------------------------------------------------------------------
extern "C" void kernel_launch(void* const* d_in, const int* in_sizes, int n_in,
                              void* d_out, int out_size)
{
    const float* x     = (const float*)d_in[0];
    const float* Wf    = (const float*)d_in[1];
    const float* Wd    = (const float*)d_in[2];
    const float* gamma = (const float*)d_in[3];
    const float* beta  = (const float*)d_in[4];
    float* out = (float*)d_out;

    (void)cudaFuncSetAttribute(gemm_mma_kernel,
                               cudaFuncAttributeMaxDynamicSharedMemorySize, SMEM_TOTAL);

    convert_w_kernel<<<MTOT, CIN>>>(Wf, Wd);

    dim3 tgrid(LQ / 32, CIN / 32, BQ);
    transpose_split_kernel<<<tgrid, dim3(32, 8)>>>(x);

    zero_stats_kernel<<<1, COUT>>>();          // GEMM stays launch #4 (ncu target)

    dim3 ggrid(MTOT / BM, LQ / BN, BQ);        // (4, 192, 8)
    gemm_mma_kernel<<<ggrid, 256, SMEM_TOTAL>>>();

    stats_kernel<<<dim3(COUT, BQ), 256>>>();
    finalize_kernel<<<1, COUT>>>(gamma, beta);
    epilogue_kernel<<<dim3(NPTS / 256, COUT, BQ), 256>>>(out);
}

// round 11
// speedup vs baseline: 1.2495x; 1.2495x over previous
#include <cuda_runtime.h>
#include <cuda_bf16.h>
#include <math.h>
#include <stdint.h>

// Problem constants
#define BQ    8
#define CIN   256
#define COUT  256
#define NPTS  8192
#define LQ    (3 * NPTS)      // 24576 columns per (batch) GEMM
#define MTOT  (2 * COUT)      // 512 rows: [W_feat; W_dir]

// GEMM tiling (R4-proven shape)
#define BM 128
#define BN 128
#define BK 32
#define KEFF 768              // 3 split passes x 256
#define NKC  (KEFF / BK)      // 24 k-chunks
#define NSTAGE 5
#define LOOKAHEAD 3

// SMEM: rows of 64B data padded to 80B pitch (conflict-free ldmatrix)
#define ROWP 80
#define TILE_BYTES (128 * ROWP)           // 10240
#define STAGE_BYTES (2 * TILE_BYTES)      // A + B = 20480
#define SMEM_TOTAL (NSTAGE * STAGE_BYTES) // 102400 (x2 CTA = 200KB <= 227KB)

// ---------------------------------------------------------------------------
// Static device scratch (no runtime allocation)
// ---------------------------------------------------------------------------
__device__ float g_p[(size_t)BQ * COUT * LQ];   // 192 MiB
__device__ float g_d[(size_t)BQ * COUT * LQ];   // 192 MiB
__device__ __nv_bfloat16 g_xhi[(size_t)BQ * LQ * CIN];  // transposed [b, l, k]
__device__ __nv_bfloat16 g_xlo[(size_t)BQ * LQ * CIN];
__device__ __nv_bfloat16 g_whi[MTOT * CIN];
__device__ __nv_bfloat16 g_wlo[MTOT * CIN];
__device__ float g_sum[COUT];
__device__ float g_sumsq[COUT];
__device__ float g_bn_a[COUT];
__device__ float g_bn_b[COUT];

// ---------------------------------------------------------------------------
// PTX helpers (sm_80-era: valid for plain sm_103 target)
// ---------------------------------------------------------------------------
__device__ __forceinline__ uint32_t smem_u32(const void* p) {
    uint32_t a;
    asm("{ .reg .u64 t; cvta.to.shared.u64 t, %1; cvt.u32.u64 %0, t; }" : "=r"(a) : "l"(p));
    return a;
}

__device__ __forceinline__ void cp16(uint32_t dst, const void* src) {
    asm volatile("cp.async.cg.shared.global [%0], [%1], 16;" :: "r"(dst), "l"(src) : "memory");
}
#define CP_COMMIT() asm volatile("cp.async.commit_group;" ::: "memory")
#define CP_WAIT(n)  asm volatile("cp.async.wait_group %0;" :: "n"(n) : "memory")

__device__ __forceinline__ void ldsm4(uint32_t* r, uint32_t addr) {
    asm volatile("ldmatrix.sync.aligned.m8n8.x4.shared.b16 {%0,%1,%2,%3}, [%4];"
                 : "=r"(r[0]), "=r"(r[1]), "=r"(r[2]), "=r"(r[3]) : "r"(addr));
}

__device__ __forceinline__ void mma16816(float* c, const uint32_t* a,
                                         uint32_t b0, uint32_t b1) {
    asm volatile(
        "mma.sync.aligned.m16n8k16.row.col.f32.bf16.bf16.f32 "
        "{%0,%1,%2,%3}, {%4,%5,%6,%7}, {%8,%9}, {%0,%1,%2,%3};"
        : "+f"(c[0]), "+f"(c[1]), "+f"(c[2]), "+f"(c[3])
        : "r"(a[0]), "r"(a[1]), "r"(a[2]), "r"(a[3]), "r"(b0), "r"(b1));
}

// ---------------------------------------------------------------------------
// K_a: W -> concatenated bf16 hi/lo [512, 256]
// ---------------------------------------------------------------------------
__global__ void convert_w_kernel(const float* __restrict__ Wf, const float* __restrict__ Wd)
{
    int row = blockIdx.x;
    int col = threadIdx.x;
    float v = (row < COUT) ? Wf[row * CIN + col] : Wd[(row - COUT) * CIN + col];
    __nv_bfloat16 hi = __float2bfloat16(v);
    float r = v - __bfloat162float(hi);
    g_whi[row * CIN + col] = hi;
    g_wlo[row * CIN + col] = __float2bfloat16(r);
}

// ---------------------------------------------------------------------------
// K_b: x [b, k, l] fp32 -> Xt_hi/Xt_lo [b, l, k] bf16 (transpose + split)
// ---------------------------------------------------------------------------
__global__ __launch_bounds__(256)
void transpose_split_kernel(const float* __restrict__ x)
{
    __shared__ float s[32][33];
    const int b  = blockIdx.z;
    const int k0 = blockIdx.y * 32;
    const int l0 = blockIdx.x * 32;
    const int tx = threadIdx.x, ty = threadIdx.y;

    const float* xb = x + ((size_t)b * CIN + k0) * LQ + l0;
#pragma unroll
    for (int i = 0; i < 4; i++) {
        int k = ty + i * 8;
        s[k][tx] = xb[(size_t)k * LQ + tx];
    }
    __syncthreads();
#pragma unroll
    for (int i = 0; i < 4; i++) {
        int lr = ty + i * 8;
        float v = s[tx][lr];
        __nv_bfloat16 hi = __float2bfloat16(v);
        float r = v - __bfloat162float(hi);
        size_t off = ((size_t)b * LQ + l0 + lr) * CIN + k0 + tx;
        g_xhi[off] = hi;
        g_xlo[off] = __float2bfloat16(r);
    }
}

// ---------------------------------------------------------------------------
// K1: mma.sync bf16 GEMM  C[512, 24576] (3-pass split) per batch
// grid (4 m, 192 l, 8 b), 256 threads, 8 warps as 4(m) x 2(n), warp m32xn64
// 5-stage cp.async pipeline; load issued BEFORE wait (stage reuse distance 2)
// ---------------------------------------------------------------------------
__global__ __launch_bounds__(256, 2)
void gemm_mma_kernel()
{
    extern __shared__ char smem[];            // NSTAGE * STAGE_BYTES
    const uint32_t su = smem_u32(smem);

    const int tid  = threadIdx.x;
    const int lane = tid & 31;
    const int w    = tid >> 5;
    const int wm   = w >> 1;                  // 0..3 -> 32 m rows each
    const int wn   = w & 1;                   // 0..1 -> 64 l cols each

    const int m0 = blockIdx.x * BM;           // 0,128,256,384 concat rows
    const int l0 = blockIdx.y * BN;
    const int b  = blockIdx.z;
    const size_t blbase = (size_t)b * LQ + l0;

    float acc[2][8][4];                       // 64 regs (warp m32 x n64)
#pragma unroll
    for (int i = 0; i < 2; i++)
#pragma unroll
        for (int j = 0; j < 8; j++)
#pragma unroll
            for (int q = 0; q < 4; q++) acc[i][j][q] = 0.f;

    const int f0 = tid * 2;                   // this thread's two 16B chunks
    auto load_stage = [&](int st, int kc) {
        const int seg  = kc >> 3;             // 0,1,2
        const int koff = (kc & 7) * BK;
        const __nv_bfloat16* Asrc = (seg < 2) ? g_whi : g_wlo;
        const __nv_bfloat16* Bsrc = (seg == 1) ? g_xlo : g_xhi;
        const uint32_t abase = su + st * STAGE_BYTES;
        const uint32_t bbase = abase + TILE_BYTES;
#pragma unroll
        for (int i = 0; i < 2; i++) {
            int f   = f0 + i;                 // 0..511
            int row = f >> 2;
            int ch  = f & 3;
            cp16(abase + row * ROWP + ch * 16,
                 Asrc + (size_t)(m0 + row) * CIN + koff + ch * 8);
            cp16(bbase + row * ROWP + ch * 16,
                 Bsrc + (blbase + row) * CIN + koff + ch * 8);
        }
        CP_COMMIT();
    };

    // Prologue: fill 3 stages
    load_stage(0, 0);
    load_stage(1, 1);
    load_stage(2, 2);

    const int lrow  = lane & 15;
    const int lhalf = lane >> 4;

    int st = 0;
    for (int kc = 0; kc < NKC; kc++) {
        // Early load: with NSTAGE=5 the target stage held chunk kc-2, whose
        // reads were completed by ALL warps at the previous iteration's
        // barrier -> safe to overwrite before this iteration's wait/barrier.
        if (kc + LOOKAHEAD < NKC) {
            int nst = st + LOOKAHEAD; if (nst >= NSTAGE) nst -= NSTAGE;
            load_stage(nst, kc + LOOKAHEAD);
        } else {
            CP_COMMIT();                       // empty group: exact wait math
        }
        CP_WAIT(LOOKAHEAD);                    // chunk kc complete (4 in flight max)
        __syncthreads();                       // all warps done with stage kc-1

        const uint32_t abase = su + st * STAGE_BYTES;
        const uint32_t bbase = abase + TILE_BYTES;

#pragma unroll
        for (int kk = 0; kk < 2; kk++) {       // two k16 steps in BK=32
            uint32_t a[2][4], bf[4][4];
#pragma unroll
            for (int i = 0; i < 2; i++)
                ldsm4(a[i], abase + (wm * 32 + i * 16 + lrow) * ROWP
                                  + (kk * 16 + lhalf * 8) * 2);
#pragma unroll
            for (int j = 0; j < 4; j++)
                ldsm4(bf[j], bbase + (wn * 64 + j * 16 + lrow) * ROWP
                                   + (kk * 16 + lhalf * 8) * 2);
#pragma unroll
            for (int i = 0; i < 2; i++)
#pragma unroll
                for (int j = 0; j < 4; j++) {
                    mma16816(acc[i][2 * j],     a[i], bf[j][0], bf[j][2]);
                    mma16816(acc[i][2 * j + 1], a[i], bf[j][1], bf[j][3]);
                }
        }
        st++; if (st >= NSTAGE) st -= NSTAGE;
    }

    // Epilogue: fragment -> g_p / g_d
    float* buf = (m0 < COUT) ? g_p : g_d;
#pragma unroll
    for (int i = 0; i < 2; i++) {
        int mrow0 = (m0 & (COUT - 1)) + wm * 32 + i * 16 + (lane >> 2);
#pragma unroll
        for (int j = 0; j < 8; j++) {
            int cg = l0 + wn * 64 + j * 8 + (lane & 3) * 2;
            float2 v0 = make_float2(acc[i][j][0], acc[i][j][1]);
            float2 v1 = make_float2(acc[i][j][2], acc[i][j][3]);
            *reinterpret_cast<float2*>(buf + ((size_t)b * COUT + mrow0) * LQ + cg)     = v0;
            *reinterpret_cast<float2*>(buf + ((size_t)b * COUT + mrow0 + 8) * LQ + cg) = v1;
        }
    }
}

// ---------------------------------------------------------------------------
// K0: zero stats accumulators
// ---------------------------------------------------------------------------
__global__ void zero_stats_kernel()
{
    int i = threadIdx.x;
    g_sum[i]   = 0.f;
    g_sumsq[i] = 0.f;
}

// ---------------------------------------------------------------------------
// K2: per-channel sum / sumsq of vector norms
// ---------------------------------------------------------------------------
__global__ __launch_bounds__(256)
void stats_kernel()
{
    const int o = blockIdx.x;
    const int b = blockIdx.y;
    const float* base = g_p + ((size_t)b * COUT + o) * LQ;

    float s = 0.f, s2 = 0.f;
    for (int n = threadIdx.x; n < NPTS; n += 256) {
        float px = base[n];
        float py = base[NPTS + n];
        float pz = base[2 * NPTS + n];
        float nrm = sqrtf(px * px + py * py + pz * pz);
        s  += nrm;
        s2 += nrm * nrm;
    }
#pragma unroll
    for (int off = 16; off > 0; off >>= 1) {
        s  += __shfl_down_sync(0xffffffffu, s,  off);
        s2 += __shfl_down_sync(0xffffffffu, s2, off);
    }
    __shared__ float shs[8], shs2[8];
    int wid = threadIdx.x >> 5;
    int lid = threadIdx.x & 31;
    if (lid == 0) { shs[wid] = s; shs2[wid] = s2; }
    __syncthreads();
    if (threadIdx.x == 0) {
        float ts = 0.f, ts2 = 0.f;
#pragma unroll
        for (int w = 0; w < 8; w++) { ts += shs[w]; ts2 += shs2[w]; }
        atomicAdd(&g_sum[o],   ts);
        atomicAdd(&g_sumsq[o], ts2);
    }
}

// ---------------------------------------------------------------------------
// K3: finalize BN affine per channel
// ---------------------------------------------------------------------------
__global__ void finalize_kernel(const float* __restrict__ gamma,
                                const float* __restrict__ beta)
{
    int o = threadIdx.x;
    const float inv = 1.0f / (float)(BQ * NPTS);
    float mean = g_sum[o] * inv;
    float var  = g_sumsq[o] * inv - mean * mean;
    float rstd = rsqrtf(var + 1e-5f);
    float a = rstd * gamma[o];
    g_bn_a[o] = a;
    g_bn_b[o] = beta[o] - mean * a;
}

// ---------------------------------------------------------------------------
// K4: BN rescale + VN LeakyReLU
// ---------------------------------------------------------------------------
__global__ __launch_bounds__(256)
void epilogue_kernel(float* __restrict__ out)
{
    const int n = blockIdx.x * 256 + threadIdx.x;
    const int o = blockIdx.y;
    const int b = blockIdx.z;
    const size_t base = ((size_t)b * COUT + o) * LQ + n;

    float px = g_p[base];
    float py = g_p[base + NPTS];
    float pz = g_p[base + 2 * NPTS];
    float dx = g_d[base];
    float dy = g_d[base + NPTS];
    float dz = g_d[base + 2 * NPTS];

    float nrm = sqrtf(px * px + py * py + pz * pz);
    float f = __ldg(&g_bn_a[o]) + __ldg(&g_bn_b[o]) / nrm;
    px *= f; py *= f; pz *= f;

    float dot = px * dx + py * dy + pz * dz;
    float dsq = dx * dx + dy * dy + dz * dz;
    if (dot < 0.f) {
        float c = 0.8f * dot / (dsq + 1e-6f);
        px -= c * dx; py -= c * dy; pz -= c * dz;
    }
    out[base]            = px;
    out[base + NPTS]     = py;
    out[base + 2 * NPTS] = pz;
}

// ---------------------------------------------------------------------------
extern "C" void kernel_launch(void* const* d_in, const int* in_sizes, int n_in,
                              void* d_out, int out_size)
{
    const float* x     = (const float*)d_in[0];
    const float* Wf    = (const float*)d_in[1];
    const float* Wd    = (const float*)d_in[2];
    const float* gamma = (const float*)d_in[3];
    const float* beta  = (const float*)d_in[4];
    float* out = (float*)d_out;

    (void)cudaFuncSetAttribute(gemm_mma_kernel,
                               cudaFuncAttributeMaxDynamicSharedMemorySize, SMEM_TOTAL);

    convert_w_kernel<<<MTOT, CIN>>>(Wf, Wd);

    dim3 tgrid(LQ / 32, CIN / 32, BQ);
    transpose_split_kernel<<<tgrid, dim3(32, 8)>>>(x);

    zero_stats_kernel<<<1, COUT>>>();          // GEMM stays launch #4 (ncu target)

    dim3 ggrid(MTOT / BM, LQ / BN, BQ);        // (4, 192, 8)
    gemm_mma_kernel<<<ggrid, 256, SMEM_TOTAL>>>();

    stats_kernel<<<dim3(COUT, BQ), 256>>>();
    finalize_kernel<<<1, COUT>>>(gamma, beta);
    epilogue_kernel<<<dim3(NPTS / 256, COUT, BQ), 256>>>(out);
}

// round 12
// speedup vs baseline: 1.3410x; 1.0732x over previous
#include <cuda_runtime.h>
#include <cuda_bf16.h>
#include <math.h>
#include <stdint.h>

// Problem constants
#define BQ    8
#define CIN   256
#define COUT  256
#define NPTS  8192
#define LQ    (3 * NPTS)      // 24576 columns per (batch) GEMM
#define MTOT  (2 * COUT)      // 512 rows: [W_feat; W_dir]

// GEMM tiling (R4/R11-proven shape)
#define BM 128
#define BN 128
#define BK 32
#define KEFF 768              // 3 split passes x 256
#define NKC  (KEFF / BK)      // 24 k-chunks (processed in 12 pairs)
#define NSTAGE 5

// SMEM: rows of 64B data padded to 80B pitch (conflict-free ldmatrix)
#define ROWP 80
#define TILE_BYTES (128 * ROWP)           // 10240
#define STAGE_BYTES (2 * TILE_BYTES)      // A + B = 20480
#define SMEM_TOTAL (NSTAGE * STAGE_BYTES) // 102400 (x2 CTA = 200KB <= 227KB)

// ---------------------------------------------------------------------------
// Static device scratch (no runtime allocation)
// ---------------------------------------------------------------------------
__device__ float g_p[(size_t)BQ * COUT * LQ];   // 192 MiB
__device__ float g_d[(size_t)BQ * COUT * LQ];   // 192 MiB
__device__ __nv_bfloat16 g_xhi[(size_t)BQ * LQ * CIN];  // transposed [b, l, k]
__device__ __nv_bfloat16 g_xlo[(size_t)BQ * LQ * CIN];
__device__ __nv_bfloat16 g_whi[MTOT * CIN];
__device__ __nv_bfloat16 g_wlo[MTOT * CIN];
__device__ float g_sum[COUT];
__device__ float g_sumsq[COUT];
__device__ float g_bn_a[COUT];
__device__ float g_bn_b[COUT];

// ---------------------------------------------------------------------------
// PTX helpers (sm_80-era: valid for plain sm_103 target)
// ---------------------------------------------------------------------------
__device__ __forceinline__ uint32_t smem_u32(const void* p) {
    uint32_t a;
    asm("{ .reg .u64 t; cvta.to.shared.u64 t, %1; cvt.u32.u64 %0, t; }" : "=r"(a) : "l"(p));
    return a;
}

__device__ __forceinline__ void cp16(uint32_t dst, const void* src) {
    asm volatile("cp.async.cg.shared.global [%0], [%1], 16;" :: "r"(dst), "l"(src) : "memory");
}
#define CP_COMMIT() asm volatile("cp.async.commit_group;" ::: "memory")
#define CP_WAIT(n)  asm volatile("cp.async.wait_group %0;" :: "n"(n) : "memory")

__device__ __forceinline__ void ldsm4(uint32_t* r, uint32_t addr) {
    asm volatile("ldmatrix.sync.aligned.m8n8.x4.shared.b16 {%0,%1,%2,%3}, [%4];"
                 : "=r"(r[0]), "=r"(r[1]), "=r"(r[2]), "=r"(r[3]) : "r"(addr));
}

__device__ __forceinline__ void mma16816(float* c, const uint32_t* a,
                                         uint32_t b0, uint32_t b1) {
    asm volatile(
        "mma.sync.aligned.m16n8k16.row.col.f32.bf16.bf16.f32 "
        "{%0,%1,%2,%3}, {%4,%5,%6,%7}, {%8,%9}, {%0,%1,%2,%3};"
        : "+f"(c[0]), "+f"(c[1]), "+f"(c[2]), "+f"(c[3])
        : "r"(a[0]), "r"(a[1]), "r"(a[2]), "r"(a[3]), "r"(b0), "r"(b1));
}

// ---------------------------------------------------------------------------
// K_a: W -> concatenated bf16 hi/lo [512, 256]
// ---------------------------------------------------------------------------
__global__ void convert_w_kernel(const float* __restrict__ Wf, const float* __restrict__ Wd)
{
    int row = blockIdx.x;
    int col = threadIdx.x;
    float v = (row < COUT) ? Wf[row * CIN + col] : Wd[(row - COUT) * CIN + col];
    __nv_bfloat16 hi = __float2bfloat16(v);
    float r = v - __bfloat162float(hi);
    g_whi[row * CIN + col] = hi;
    g_wlo[row * CIN + col] = __float2bfloat16(r);
}

// ---------------------------------------------------------------------------
// K_b: x [b, k, l] fp32 -> Xt_hi/Xt_lo [b, l, k] bf16 (transpose + split)
// ---------------------------------------------------------------------------
__global__ __launch_bounds__(256)
void transpose_split_kernel(const float* __restrict__ x)
{
    __shared__ float s[32][33];
    const int b  = blockIdx.z;
    const int k0 = blockIdx.y * 32;
    const int l0 = blockIdx.x * 32;
    const int tx = threadIdx.x, ty = threadIdx.y;

    const float* xb = x + ((size_t)b * CIN + k0) * LQ + l0;
#pragma unroll
    for (int i = 0; i < 4; i++) {
        int k = ty + i * 8;
        s[k][tx] = xb[(size_t)k * LQ + tx];
    }
    __syncthreads();
#pragma unroll
    for (int i = 0; i < 4; i++) {
        int lr = ty + i * 8;
        float v = s[tx][lr];
        __nv_bfloat16 hi = __float2bfloat16(v);
        float r = v - __bfloat162float(hi);
        size_t off = ((size_t)b * LQ + l0 + lr) * CIN + k0 + tx;
        g_xhi[off] = hi;
        g_xlo[off] = __float2bfloat16(r);
    }
}

// ---------------------------------------------------------------------------
// K1: mma.sync bf16 GEMM  C[512, 24576] (3-pass split) per batch
// grid (4 m, 192 l, 8 b), 256 threads, 8 warps as 4(m) x 2(n), warp m32xn64
// 5-stage cp.async pipeline, chunk PAIRS with one barrier per pair
// ---------------------------------------------------------------------------
__global__ __launch_bounds__(256, 2)
void gemm_mma_kernel()
{
    extern __shared__ char smem[];            // NSTAGE * STAGE_BYTES
    const uint32_t su = smem_u32(smem);

    const int tid  = threadIdx.x;
    const int lane = tid & 31;
    const int w    = tid >> 5;
    const int wm   = w >> 1;                  // 0..3 -> 32 m rows each
    const int wn   = w & 1;                   // 0..1 -> 64 l cols each

    const int m0 = blockIdx.x * BM;           // 0,128,256,384 concat rows
    const int l0 = blockIdx.y * BN;
    const int b  = blockIdx.z;
    const size_t blbase = (size_t)b * LQ + l0;

    float acc[2][8][4];                       // 64 regs (warp m32 x n64)
#pragma unroll
    for (int i = 0; i < 2; i++)
#pragma unroll
        for (int j = 0; j < 8; j++)
#pragma unroll
            for (int q = 0; q < 4; q++) acc[i][j][q] = 0.f;

    const int f0 = tid * 2;                   // this thread's two 16B chunks
    auto load_stage = [&](int st, int kc) {
        const int seg  = kc >> 3;             // 0,1,2
        const int koff = (kc & 7) * BK;
        const __nv_bfloat16* Asrc = (seg < 2) ? g_whi : g_wlo;
        const __nv_bfloat16* Bsrc = (seg == 1) ? g_xlo : g_xhi;
        const uint32_t abase = su + st * STAGE_BYTES;
        const uint32_t bbase = abase + TILE_BYTES;
#pragma unroll
        for (int i = 0; i < 2; i++) {
            int f   = f0 + i;                 // 0..511
            int row = f >> 2;
            int ch  = f & 3;
            cp16(abase + row * ROWP + ch * 16,
                 Asrc + (size_t)(m0 + row) * CIN + koff + ch * 8);
            cp16(bbase + row * ROWP + ch * 16,
                 Bsrc + (blbase + row) * CIN + koff + ch * 8);
        }
        CP_COMMIT();
    };

    // Prologue: fill 3 stages (chunks 0,1,2)
    load_stage(0, 0);
    load_stage(1, 1);
    load_stage(2, 2);

    const int lrow  = lane & 15;
    const int lhalf = lane >> 4;

    auto compute_chunk = [&](int st) {
        const uint32_t abase = su + st * STAGE_BYTES;
        const uint32_t bbase = abase + TILE_BYTES;
#pragma unroll
        for (int kk = 0; kk < 2; kk++) {       // two k16 steps in BK=32
            uint32_t a[2][4], bf[4][4];
#pragma unroll
            for (int i = 0; i < 2; i++)
                ldsm4(a[i], abase + (wm * 32 + i * 16 + lrow) * ROWP
                                  + (kk * 16 + lhalf * 8) * 2);
#pragma unroll
            for (int j = 0; j < 4; j++)
                ldsm4(bf[j], bbase + (wn * 64 + j * 16 + lrow) * ROWP
                                   + (kk * 16 + lhalf * 8) * 2);
#pragma unroll
            for (int i = 0; i < 2; i++)
#pragma unroll
                for (int j = 0; j < 4; j++) {
                    mma16816(acc[i][2 * j],     a[i], bf[j][0], bf[j][2]);
                    mma16816(acc[i][2 * j + 1], a[i], bf[j][1], bf[j][3]);
                }
        }
    };

    // Main loop: 12 chunk-pairs, ONE barrier per pair.
    // Safety (NSTAGE=5): after the pair barrier all warps are past chunk kc-1.
    // In-pair loads target stages (kc+3)%5 and (kc+4)%5, which differ from the
    // stages (kc)%5 and (kc+1)%5 that skewed warps may still be reading.
    int st = 0;                                // = kc % NSTAGE
    for (int kc = 0; kc < NKC; kc += 2) {
        CP_WAIT(2);                            // chunk kc arrived (kc+1,kc+2 pending)
        __syncthreads();                       // all warps done through chunk kc-1

        int st3 = st + 3; if (st3 >= NSTAGE) st3 -= NSTAGE;
        if (kc + 3 < NKC) load_stage(st3, kc + 3); else CP_COMMIT();

        compute_chunk(st);

        int st4 = st + 4; if (st4 >= NSTAGE) st4 -= NSTAGE;
        if (kc + 4 < NKC) load_stage(st4, kc + 4); else CP_COMMIT();

        CP_WAIT(3);                            // chunk kc+1 arrived (kc+2..kc+4 pending)
        int st1 = st + 1; if (st1 >= NSTAGE) st1 -= NSTAGE;
        compute_chunk(st1);

        st += 2; if (st >= NSTAGE) st -= NSTAGE;
    }

    // Epilogue: fragment -> g_p / g_d
    float* buf = (m0 < COUT) ? g_p : g_d;
#pragma unroll
    for (int i = 0; i < 2; i++) {
        int mrow0 = (m0 & (COUT - 1)) + wm * 32 + i * 16 + (lane >> 2);
#pragma unroll
        for (int j = 0; j < 8; j++) {
            int cg = l0 + wn * 64 + j * 8 + (lane & 3) * 2;
            float2 v0 = make_float2(acc[i][j][0], acc[i][j][1]);
            float2 v1 = make_float2(acc[i][j][2], acc[i][j][3]);
            *reinterpret_cast<float2*>(buf + ((size_t)b * COUT + mrow0) * LQ + cg)     = v0;
            *reinterpret_cast<float2*>(buf + ((size_t)b * COUT + mrow0 + 8) * LQ + cg) = v1;
        }
    }
}

// ---------------------------------------------------------------------------
// K0: zero stats accumulators
// ---------------------------------------------------------------------------
__global__ void zero_stats_kernel()
{
    int i = threadIdx.x;
    g_sum[i]   = 0.f;
    g_sumsq[i] = 0.f;
}

// ---------------------------------------------------------------------------
// K2: per-channel sum / sumsq of vector norms (float4 vectorized)
// grid: (COUT, BQ); block: 256; 8192 pts = 256 thr x 4 x 8 iters
// ---------------------------------------------------------------------------
__global__ __launch_bounds__(256)
void stats_kernel()
{
    const int o = blockIdx.x;
    const int b = blockIdx.y;
    const float* base = g_p + ((size_t)b * COUT + o) * LQ;

    float s = 0.f, s2 = 0.f;
#pragma unroll
    for (int it = 0; it < NPTS / (256 * 4); it++) {
        int n = (it * 256 + threadIdx.x) * 4;
        float4 px = *reinterpret_cast<const float4*>(base + n);
        float4 py = *reinterpret_cast<const float4*>(base + NPTS + n);
        float4 pz = *reinterpret_cast<const float4*>(base + 2 * NPTS + n);
        float q0 = px.x * px.x + py.x * py.x + pz.x * pz.x;
        float q1 = px.y * px.y + py.y * py.y + pz.y * pz.y;
        float q2 = px.z * px.z + py.z * py.z + pz.z * pz.z;
        float q3 = px.w * px.w + py.w * py.w + pz.w * pz.w;
        s  += sqrtf(q0) + sqrtf(q1) + sqrtf(q2) + sqrtf(q3);
        s2 += q0 + q1 + q2 + q3;
    }
#pragma unroll
    for (int off = 16; off > 0; off >>= 1) {
        s  += __shfl_down_sync(0xffffffffu, s,  off);
        s2 += __shfl_down_sync(0xffffffffu, s2, off);
    }
    __shared__ float shs[8], shs2[8];
    int wid = threadIdx.x >> 5;
    int lid = threadIdx.x & 31;
    if (lid == 0) { shs[wid] = s; shs2[wid] = s2; }
    __syncthreads();
    if (threadIdx.x == 0) {
        float ts = 0.f, ts2 = 0.f;
#pragma unroll
        for (int w = 0; w < 8; w++) { ts += shs[w]; ts2 += shs2[w]; }
        atomicAdd(&g_sum[o],   ts);
        atomicAdd(&g_sumsq[o], ts2);
    }
}

// ---------------------------------------------------------------------------
// K3: finalize BN affine per channel
// ---------------------------------------------------------------------------
__global__ void finalize_kernel(const float* __restrict__ gamma,
                                const float* __restrict__ beta)
{
    int o = threadIdx.x;
    const float inv = 1.0f / (float)(BQ * NPTS);
    float mean = g_sum[o] * inv;
    float var  = g_sumsq[o] * inv - mean * mean;
    float rstd = rsqrtf(var + 1e-5f);
    float a = rstd * gamma[o];
    g_bn_a[o] = a;
    g_bn_b[o] = beta[o] - mean * a;
}

// ---------------------------------------------------------------------------
// K4: BN rescale + VN LeakyReLU (float4 vectorized: 4 points per thread)
// grid: (NPTS/1024, COUT, BQ); block 256
// ---------------------------------------------------------------------------
__global__ __launch_bounds__(256)
void epilogue_kernel(float* __restrict__ out)
{
    const int n = (blockIdx.x * 256 + threadIdx.x) * 4;
    const int o = blockIdx.y;
    const int b = blockIdx.z;
    const size_t base = ((size_t)b * COUT + o) * LQ + n;

    float4 px = *reinterpret_cast<const float4*>(g_p + base);
    float4 py = *reinterpret_cast<const float4*>(g_p + base + NPTS);
    float4 pz = *reinterpret_cast<const float4*>(g_p + base + 2 * NPTS);
    float4 dx = *reinterpret_cast<const float4*>(g_d + base);
    float4 dy = *reinterpret_cast<const float4*>(g_d + base + NPTS);
    float4 dz = *reinterpret_cast<const float4*>(g_d + base + 2 * NPTS);

    const float bna = __ldg(&g_bn_a[o]);
    const float bnb = __ldg(&g_bn_b[o]);

    float opx[4], opy[4], opz[4];
    const float* pxs = &px.x; const float* pys = &py.x; const float* pzs = &pz.x;
    const float* dxs = &dx.x; const float* dys = &dy.x; const float* dzs = &dz.x;
#pragma unroll
    for (int q = 0; q < 4; q++) {
        float ax = pxs[q], ay = pys[q], az = pzs[q];
        float ex = dxs[q], ey = dys[q], ez = dzs[q];
        float nrm = sqrtf(ax * ax + ay * ay + az * az);
        float f = bna + bnb / nrm;
        ax *= f; ay *= f; az *= f;
        float dot = ax * ex + ay * ey + az * ez;
        float dsq = ex * ex + ey * ey + ez * ez;
        if (dot < 0.f) {
            float c = 0.8f * dot / (dsq + 1e-6f);
            ax -= c * ex; ay -= c * ey; az -= c * ez;
        }
        opx[q] = ax; opy[q] = ay; opz[q] = az;
    }
    *reinterpret_cast<float4*>(out + base)            = make_float4(opx[0], opx[1], opx[2], opx[3]);
    *reinterpret_cast<float4*>(out + base + NPTS)     = make_float4(opy[0], opy[1], opy[2], opy[3]);
    *reinterpret_cast<float4*>(out + base + 2 * NPTS) = make_float4(opz[0], opz[1], opz[2], opz[3]);
}

// ---------------------------------------------------------------------------
extern "C" void kernel_launch(void* const* d_in, const int* in_sizes, int n_in,
                              void* d_out, int out_size)
{
    const float* x     = (const float*)d_in[0];
    const float* Wf    = (const float*)d_in[1];
    const float* Wd    = (const float*)d_in[2];
    const float* gamma = (const float*)d_in[3];
    const float* beta  = (const float*)d_in[4];
    float* out = (float*)d_out;

    (void)cudaFuncSetAttribute(gemm_mma_kernel,
                               cudaFuncAttributeMaxDynamicSharedMemorySize, SMEM_TOTAL);

    convert_w_kernel<<<MTOT, CIN>>>(Wf, Wd);

    dim3 tgrid(LQ / 32, CIN / 32, BQ);
    transpose_split_kernel<<<tgrid, dim3(32, 8)>>>(x);

    zero_stats_kernel<<<1, COUT>>>();          // GEMM stays launch #4 (ncu target)

    dim3 ggrid(MTOT / BM, LQ / BN, BQ);        // (4, 192, 8)
    gemm_mma_kernel<<<ggrid, 256, SMEM_TOTAL>>>();

    stats_kernel<<<dim3(COUT, BQ), 256>>>();
    finalize_kernel<<<1, COUT>>>(gamma, beta);
    epilogue_kernel<<<dim3(NPTS / 1024, COUT, BQ), 256>>>(out);
}

// round 13
// speedup vs baseline: 1.7601x; 1.3125x over previous
#include <cuda_runtime.h>
#include <cuda_fp16.h>
#include <math.h>
#include <stdint.h>

// Problem constants
#define BQ    8
#define CIN   256
#define COUT  256
#define NPTS  8192
#define LQ    (3 * NPTS)      // 24576 columns per (batch) GEMM
#define MTOT  (2 * COUT)      // 512 rows: [W_feat; W_dir]

// GEMM tiling (R4/R11/R12-proven shape)
#define BM 128
#define BN 128
#define BK 32
#define KEFF 512              // 2 split passes x 256 (fp16 split-W)
#define NKC  (KEFF / BK)      // 16 k-chunks (8 pairs)
#define NSTAGE 5

// SMEM: rows of 64B data padded to 80B pitch (conflict-free ldmatrix)
#define ROWP 80
#define TILE_BYTES (128 * ROWP)           // 10240
#define STAGE_BYTES (2 * TILE_BYTES)      // A + B = 20480
#define SMEM_TOTAL (NSTAGE * STAGE_BYTES) // 102400 (x2 CTA = 200KB <= 227KB)

// ---------------------------------------------------------------------------
// Static device scratch (no runtime allocation)
// ---------------------------------------------------------------------------
__device__ float g_p[(size_t)BQ * COUT * LQ];   // 192 MiB
__device__ float g_d[(size_t)BQ * COUT * LQ];   // 192 MiB
__device__ __half g_xt[(size_t)BQ * LQ * CIN];  // transposed [b, l, k] fp16
__device__ __half g_whi[MTOT * CIN];
__device__ __half g_wlo[MTOT * CIN];
__device__ float g_sum[COUT];
__device__ float g_sumsq[COUT];
__device__ float g_bn_a[COUT];
__device__ float g_bn_b[COUT];

// ---------------------------------------------------------------------------
// PTX helpers (sm_80-era: valid for plain sm_103 target)
// ---------------------------------------------------------------------------
__device__ __forceinline__ uint32_t smem_u32(const void* p) {
    uint32_t a;
    asm("{ .reg .u64 t; cvta.to.shared.u64 t, %1; cvt.u32.u64 %0, t; }" : "=r"(a) : "l"(p));
    return a;
}

__device__ __forceinline__ void cp16(uint32_t dst, const void* src) {
    asm volatile("cp.async.cg.shared.global [%0], [%1], 16;" :: "r"(dst), "l"(src) : "memory");
}
#define CP_COMMIT() asm volatile("cp.async.commit_group;" ::: "memory")
#define CP_WAIT(n)  asm volatile("cp.async.wait_group %0;" :: "n"(n) : "memory")

__device__ __forceinline__ void ldsm4(uint32_t* r, uint32_t addr) {
    asm volatile("ldmatrix.sync.aligned.m8n8.x4.shared.b16 {%0,%1,%2,%3}, [%4];"
                 : "=r"(r[0]), "=r"(r[1]), "=r"(r[2]), "=r"(r[3]) : "r"(addr));
}

__device__ __forceinline__ void mma16816(float* c, const uint32_t* a,
                                         uint32_t b0, uint32_t b1) {
    asm volatile(
        "mma.sync.aligned.m16n8k16.row.col.f32.f16.f16.f32 "
        "{%0,%1,%2,%3}, {%4,%5,%6,%7}, {%8,%9}, {%0,%1,%2,%3};"
        : "+f"(c[0]), "+f"(c[1]), "+f"(c[2]), "+f"(c[3])
        : "r"(a[0]), "r"(a[1]), "r"(a[2]), "r"(a[3]), "r"(b0), "r"(b1));
}

// ---------------------------------------------------------------------------
// K_a: W -> concatenated fp16 hi/lo [512, 256]
// ---------------------------------------------------------------------------
__global__ void convert_w_kernel(const float* __restrict__ Wf, const float* __restrict__ Wd)
{
    int row = blockIdx.x;
    int col = threadIdx.x;
    float v = (row < COUT) ? Wf[row * CIN + col] : Wd[(row - COUT) * CIN + col];
    __half hi = __float2half_rn(v);
    float r = v - __half2float(hi);
    g_whi[row * CIN + col] = hi;
    g_wlo[row * CIN + col] = __float2half_rn(r);
}

// ---------------------------------------------------------------------------
// K_b: x [b, k, l] fp32 -> Xt [b, l, k] fp16 (transpose + round)
// ---------------------------------------------------------------------------
__global__ __launch_bounds__(256)
void transpose_split_kernel(const float* __restrict__ x)
{
    __shared__ float s[32][33];
    const int b  = blockIdx.z;
    const int k0 = blockIdx.y * 32;
    const int l0 = blockIdx.x * 32;
    const int tx = threadIdx.x, ty = threadIdx.y;

    const float* xb = x + ((size_t)b * CIN + k0) * LQ + l0;
#pragma unroll
    for (int i = 0; i < 4; i++) {
        int k = ty + i * 8;
        s[k][tx] = xb[(size_t)k * LQ + tx];
    }
    __syncthreads();
#pragma unroll
    for (int i = 0; i < 4; i++) {
        int lr = ty + i * 8;
        float v = s[tx][lr];
        size_t off = ((size_t)b * LQ + l0 + lr) * CIN + k0 + tx;
        g_xt[off] = __float2half_rn(v);
    }
}

// ---------------------------------------------------------------------------
// K1: mma.sync fp16 GEMM  C[512, 24576] = (Wh + Wl) @ Xt^T  per batch
// grid (4 m, 192 l, 8 b), 256 threads, 8 warps as 4(m) x 2(n), warp m32xn64
// 5-stage cp.async pipeline, chunk PAIRS with one barrier per pair
// ---------------------------------------------------------------------------
__global__ __launch_bounds__(256, 2)
void gemm_mma_kernel()
{
    extern __shared__ char smem[];            // NSTAGE * STAGE_BYTES
    const uint32_t su = smem_u32(smem);

    const int tid  = threadIdx.x;
    const int lane = tid & 31;
    const int w    = tid >> 5;
    const int wm   = w >> 1;                  // 0..3 -> 32 m rows each
    const int wn   = w & 1;                   // 0..1 -> 64 l cols each

    const int m0 = blockIdx.x * BM;           // 0,128,256,384 concat rows
    const int l0 = blockIdx.y * BN;
    const int b  = blockIdx.z;
    const size_t blbase = (size_t)b * LQ + l0;

    float acc[2][8][4];                       // 64 regs (warp m32 x n64)
#pragma unroll
    for (int i = 0; i < 2; i++)
#pragma unroll
        for (int j = 0; j < 8; j++)
#pragma unroll
            for (int q = 0; q < 4; q++) acc[i][j][q] = 0.f;

    const int f0 = tid * 2;                   // this thread's two 16B chunks
    auto load_stage = [&](int st, int kc) {
        const int seg  = kc >> 3;             // 0: Wh pass, 1: Wl pass
        const int koff = (kc & 7) * BK;
        const __half* Asrc = (seg == 0) ? g_whi : g_wlo;
        const uint32_t abase = su + st * STAGE_BYTES;
        const uint32_t bbase = abase + TILE_BYTES;
#pragma unroll
        for (int i = 0; i < 2; i++) {
            int f   = f0 + i;                 // 0..511
            int row = f >> 2;
            int ch  = f & 3;
            cp16(abase + row * ROWP + ch * 16,
                 Asrc + (size_t)(m0 + row) * CIN + koff + ch * 8);
            cp16(bbase + row * ROWP + ch * 16,
                 g_xt + (blbase + row) * CIN + koff + ch * 8);
        }
        CP_COMMIT();
    };

    // Prologue: fill 3 stages (chunks 0,1,2)
    load_stage(0, 0);
    load_stage(1, 1);
    load_stage(2, 2);

    const int lrow  = lane & 15;
    const int lhalf = lane >> 4;

    auto compute_chunk = [&](int st) {
        const uint32_t abase = su + st * STAGE_BYTES;
        const uint32_t bbase = abase + TILE_BYTES;
#pragma unroll
        for (int kk = 0; kk < 2; kk++) {       // two k16 steps in BK=32
            uint32_t a[2][4], bf[4][4];
#pragma unroll
            for (int i = 0; i < 2; i++)
                ldsm4(a[i], abase + (wm * 32 + i * 16 + lrow) * ROWP
                                  + (kk * 16 + lhalf * 8) * 2);
#pragma unroll
            for (int j = 0; j < 4; j++)
                ldsm4(bf[j], bbase + (wn * 64 + j * 16 + lrow) * ROWP
                                   + (kk * 16 + lhalf * 8) * 2);
#pragma unroll
            for (int i = 0; i < 2; i++)
#pragma unroll
                for (int j = 0; j < 4; j++) {
                    mma16816(acc[i][2 * j],     a[i], bf[j][0], bf[j][2]);
                    mma16816(acc[i][2 * j + 1], a[i], bf[j][1], bf[j][3]);
                }
        }
    };

    // Main loop: 8 chunk-pairs, ONE barrier per pair.
    // Safety (NSTAGE=5): after the pair barrier all warps are past chunk kc-1.
    // In-pair loads target stages (kc+3)%5 and (kc+4)%5, which differ from the
    // stages (kc)%5 and (kc+1)%5 that skewed warps may still be reading.
    int st = 0;                                // = kc % NSTAGE
    for (int kc = 0; kc < NKC; kc += 2) {
        CP_WAIT(2);                            // chunk kc arrived (kc+1,kc+2 pending)
        __syncthreads();                       // all warps done through chunk kc-1

        int st3 = st + 3; if (st3 >= NSTAGE) st3 -= NSTAGE;
        if (kc + 3 < NKC) load_stage(st3, kc + 3); else CP_COMMIT();

        compute_chunk(st);

        int st4 = st + 4; if (st4 >= NSTAGE) st4 -= NSTAGE;
        if (kc + 4 < NKC) load_stage(st4, kc + 4); else CP_COMMIT();

        CP_WAIT(3);                            // chunk kc+1 arrived
        int st1 = st + 1; if (st1 >= NSTAGE) st1 -= NSTAGE;
        compute_chunk(st1);

        st += 2; if (st >= NSTAGE) st -= NSTAGE;
    }

    // Epilogue: fragment -> g_p / g_d
    float* buf = (m0 < COUT) ? g_p : g_d;
#pragma unroll
    for (int i = 0; i < 2; i++) {
        int mrow0 = (m0 & (COUT - 1)) + wm * 32 + i * 16 + (lane >> 2);
#pragma unroll
        for (int j = 0; j < 8; j++) {
            int cg = l0 + wn * 64 + j * 8 + (lane & 3) * 2;
            float2 v0 = make_float2(acc[i][j][0], acc[i][j][1]);
            float2 v1 = make_float2(acc[i][j][2], acc[i][j][3]);
            *reinterpret_cast<float2*>(buf + ((size_t)b * COUT + mrow0) * LQ + cg)     = v0;
            *reinterpret_cast<float2*>(buf + ((size_t)b * COUT + mrow0 + 8) * LQ + cg) = v1;
        }
    }
}

// ---------------------------------------------------------------------------
// K0: zero stats accumulators
// ---------------------------------------------------------------------------
__global__ void zero_stats_kernel()
{
    int i = threadIdx.x;
    g_sum[i]   = 0.f;
    g_sumsq[i] = 0.f;
}

// ---------------------------------------------------------------------------
// K2: per-channel sum / sumsq of vector norms (float4 vectorized)
// ---------------------------------------------------------------------------
__global__ __launch_bounds__(256)
void stats_kernel()
{
    const int o = blockIdx.x;
    const int b = blockIdx.y;
    const float* base = g_p + ((size_t)b * COUT + o) * LQ;

    float s = 0.f, s2 = 0.f;
#pragma unroll
    for (int it = 0; it < NPTS / (256 * 4); it++) {
        int n = (it * 256 + threadIdx.x) * 4;
        float4 px = *reinterpret_cast<const float4*>(base + n);
        float4 py = *reinterpret_cast<const float4*>(base + NPTS + n);
        float4 pz = *reinterpret_cast<const float4*>(base + 2 * NPTS + n);
        float q0 = px.x * px.x + py.x * py.x + pz.x * pz.x;
        float q1 = px.y * px.y + py.y * py.y + pz.y * pz.y;
        float q2 = px.z * px.z + py.z * py.z + pz.z * pz.z;
        float q3 = px.w * px.w + py.w * py.w + pz.w * pz.w;
        s  += sqrtf(q0) + sqrtf(q1) + sqrtf(q2) + sqrtf(q3);
        s2 += q0 + q1 + q2 + q3;
    }
#pragma unroll
    for (int off = 16; off > 0; off >>= 1) {
        s  += __shfl_down_sync(0xffffffffu, s,  off);
        s2 += __shfl_down_sync(0xffffffffu, s2, off);
    }
    __shared__ float shs[8], shs2[8];
    int wid = threadIdx.x >> 5;
    int lid = threadIdx.x & 31;
    if (lid == 0) { shs[wid] = s; shs2[wid] = s2; }
    __syncthreads();
    if (threadIdx.x == 0) {
        float ts = 0.f, ts2 = 0.f;
#pragma unroll
        for (int w = 0; w < 8; w++) { ts += shs[w]; ts2 += shs2[w]; }
        atomicAdd(&g_sum[o],   ts);
        atomicAdd(&g_sumsq[o], ts2);
    }
}

// ---------------------------------------------------------------------------
// K3: finalize BN affine per channel
// ---------------------------------------------------------------------------
__global__ void finalize_kernel(const float* __restrict__ gamma,
                                const float* __restrict__ beta)
{
    int o = threadIdx.x;
    const float inv = 1.0f / (float)(BQ * NPTS);
    float mean = g_sum[o] * inv;
    float var  = g_sumsq[o] * inv - mean * mean;
    float rstd = rsqrtf(var + 1e-5f);
    float a = rstd * gamma[o];
    g_bn_a[o] = a;
    g_bn_b[o] = beta[o] - mean * a;
}

// ---------------------------------------------------------------------------
// K4: BN rescale + VN LeakyReLU (float4 vectorized: 4 points per thread)
// ---------------------------------------------------------------------------
__global__ __launch_bounds__(256)
void epilogue_kernel(float* __restrict__ out)
{
    const int n = (blockIdx.x * 256 + threadIdx.x) * 4;
    const int o = blockIdx.y;
    const int b = blockIdx.z;
    const size_t base = ((size_t)b * COUT + o) * LQ + n;

    float4 px = *reinterpret_cast<const float4*>(g_p + base);
    float4 py = *reinterpret_cast<const float4*>(g_p + base + NPTS);
    float4 pz = *reinterpret_cast<const float4*>(g_p + base + 2 * NPTS);
    float4 dx = *reinterpret_cast<const float4*>(g_d + base);
    float4 dy = *reinterpret_cast<const float4*>(g_d + base + NPTS);
    float4 dz = *reinterpret_cast<const float4*>(g_d + base + 2 * NPTS);

    const float bna = __ldg(&g_bn_a[o]);
    const float bnb = __ldg(&g_bn_b[o]);

    float opx[4], opy[4], opz[4];
    const float* pxs = &px.x; const float* pys = &py.x; const float* pzs = &pz.x;
    const float* dxs = &dx.x; const float* dys = &dy.x; const float* dzs = &dz.x;
#pragma unroll
    for (int q = 0; q < 4; q++) {
        float ax = pxs[q], ay = pys[q], az = pzs[q];
        float ex = dxs[q], ey = dys[q], ez = dzs[q];
        float nrm = sqrtf(ax * ax + ay * ay + az * az);
        float f = bna + bnb / nrm;
        ax *= f; ay *= f; az *= f;
        float dot = ax * ex + ay * ey + az * ez;
        float dsq = ex * ex + ey * ey + ez * ez;
        if (dot < 0.f) {
            float c = 0.8f * dot / (dsq + 1e-6f);
            ax -= c * ex; ay -= c * ey; az -= c * ez;
        }
        opx[q] = ax; opy[q] = ay; opz[q] = az;
    }
    *reinterpret_cast<float4*>(out + base)            = make_float4(opx[0], opx[1], opx[2], opx[3]);
    *reinterpret_cast<float4*>(out + base + NPTS)     = make_float4(opy[0], opy[1], opy[2], opy[3]);
    *reinterpret_cast<float4*>(out + base + 2 * NPTS) = make_float4(opz[0], opz[1], opz[2], opz[3]);
}

// ---------------------------------------------------------------------------
extern "C" void kernel_launch(void* const* d_in, const int* in_sizes, int n_in,
                              void* d_out, int out_size)
{
    const float* x     = (const float*)d_in[0];
    const float* Wf    = (const float*)d_in[1];
    const float* Wd    = (const float*)d_in[2];
    const float* gamma = (const float*)d_in[3];
    const float* beta  = (const float*)d_in[4];
    float* out = (float*)d_out;

    (void)cudaFuncSetAttribute(gemm_mma_kernel,
                               cudaFuncAttributeMaxDynamicSharedMemorySize, SMEM_TOTAL);

    convert_w_kernel<<<MTOT, CIN>>>(Wf, Wd);

    dim3 tgrid(LQ / 32, CIN / 32, BQ);
    transpose_split_kernel<<<tgrid, dim3(32, 8)>>>(x);

    zero_stats_kernel<<<1, COUT>>>();          // GEMM stays launch #4 (ncu target)

    dim3 ggrid(MTOT / BM, LQ / BN, BQ);        // (4, 192, 8)
    gemm_mma_kernel<<<ggrid, 256, SMEM_TOTAL>>>();

    stats_kernel<<<dim3(COUT, BQ), 256>>>();
    finalize_kernel<<<1, COUT>>>(gamma, beta);
    epilogue_kernel<<<dim3(NPTS / 1024, COUT, BQ), 256>>>(out);
}

// round 15
// speedup vs baseline: 2.0317x; 1.1543x over previous
#include <cuda_runtime.h>
#include <cuda_fp16.h>
#include <math.h>
#include <stdint.h>

// Problem constants
#define BQ    8
#define CIN   256
#define COUT  256
#define NPTS  8192
#define LQ    (3 * NPTS)      // 24576 columns per (batch) GEMM
#define MTOT  (2 * COUT)      // 512 rows: [W_feat; W_dir]

// GEMM tiling
#define BM 128
#define BN 128
#define BK 32
#define NKC_P 16              // p rows: 2 passes (Wh, Wl)
#define NKC_D 8               // d rows: 1 pass  (Wh only)
#define NSTAGE 5

// SMEM: rows of 64B data padded to 80B pitch (conflict-free ldmatrix)
#define ROWP 80
#define TILE_BYTES (128 * ROWP)           // 10240
#define STAGE_BYTES (2 * TILE_BYTES)      // A + B = 20480
#define SMEM_TOTAL (NSTAGE * STAGE_BYTES) // 102400 (x2 CTA = 200KB <= 227KB)

// ---------------------------------------------------------------------------
// Static device scratch (no runtime allocation)
// ---------------------------------------------------------------------------
__device__ float g_p[(size_t)BQ * COUT * LQ];   // 192 MiB
__device__ float g_d[(size_t)BQ * COUT * LQ];   // 192 MiB
__device__ __half g_xt[(size_t)BQ * LQ * CIN];  // transposed [b, l, k] fp16
__device__ __half g_whi[MTOT * CIN];
__device__ __half g_wlo[MTOT * CIN];
__device__ float g_sum[COUT];
__device__ float g_sumsq[COUT];
__device__ float g_bn_a[COUT];
__device__ float g_bn_b[COUT];

// ---------------------------------------------------------------------------
// PTX helpers (sm_80-era: valid for plain sm_103 target)
// ---------------------------------------------------------------------------
__device__ __forceinline__ uint32_t smem_u32(const void* p) {
    uint32_t a;
    asm("{ .reg .u64 t; cvta.to.shared.u64 t, %1; cvt.u32.u64 %0, t; }" : "=r"(a) : "l"(p));
    return a;
}

__device__ __forceinline__ void cp16(uint32_t dst, const void* src) {
    asm volatile("cp.async.cg.shared.global [%0], [%1], 16;" :: "r"(dst), "l"(src) : "memory");
}
#define CP_COMMIT() asm volatile("cp.async.commit_group;" ::: "memory")
#define CP_WAIT(n)  asm volatile("cp.async.wait_group %0;" :: "n"(n) : "memory")

__device__ __forceinline__ void ldsm4(uint32_t* r, uint32_t addr) {
    asm volatile("ldmatrix.sync.aligned.m8n8.x4.shared.b16 {%0,%1,%2,%3}, [%4];"
                 : "=r"(r[0]), "=r"(r[1]), "=r"(r[2]), "=r"(r[3]) : "r"(addr));
}

__device__ __forceinline__ void mma16816(float* c, const uint32_t* a,
                                         uint32_t b0, uint32_t b1) {
    asm volatile(
        "mma.sync.aligned.m16n8k16.row.col.f32.f16.f16.f32 "
        "{%0,%1,%2,%3}, {%4,%5,%6,%7}, {%8,%9}, {%0,%1,%2,%3};"
        : "+f"(c[0]), "+f"(c[1]), "+f"(c[2]), "+f"(c[3])
        : "r"(a[0]), "r"(a[1]), "r"(a[2]), "r"(a[3]), "r"(b0), "r"(b1));
}

// ---------------------------------------------------------------------------
// K_a: W -> concatenated fp16 hi/lo [512, 256]
// ---------------------------------------------------------------------------
__global__ void convert_w_kernel(const float* __restrict__ Wf, const float* __restrict__ Wd)
{
    int row = blockIdx.x;
    int col = threadIdx.x;
    float v = (row < COUT) ? Wf[row * CIN + col] : Wd[(row - COUT) * CIN + col];
    __half hi = __float2half_rn(v);
    float r = v - __half2float(hi);
    g_whi[row * CIN + col] = hi;
    g_wlo[row * CIN + col] = __float2half_rn(r);
}

// ---------------------------------------------------------------------------
// K_b: x [b, k, l] fp32 -> Xt [b, l, k] fp16 (transpose + round)
// tile: l32 x k64; scalar smem reads (pitch 65 is float2-misaligned on odd
// rows -- the R14 crash), half2 coalesced gmem stores
// ---------------------------------------------------------------------------
__global__ __launch_bounds__(256)
void transpose_split_kernel(const float* __restrict__ x)
{
    __shared__ float s[32][65];               // [l][k], pitch 65 words
    const int b  = blockIdx.z;
    const int k0 = blockIdx.y * 64;
    const int l0 = blockIdx.x * 32;
    const int tx = threadIdx.x, ty = threadIdx.y;   // 32 x 8

    const float* xb = x + ((size_t)b * CIN + k0) * LQ + l0;
#pragma unroll
    for (int i = 0; i < 8; i++) {
        int k = ty + i * 8;
        s[tx][k] = xb[(size_t)k * LQ + tx];   // coalesced gmem; banks (tx+k)%32: conflict-free
    }
    __syncthreads();
#pragma unroll
    for (int i = 0; i < 4; i++) {
        int l = ty + i * 8;
        float v0 = s[l][2 * tx];              // scalar reads: 4B-aligned always
        float v1 = s[l][2 * tx + 1];
        __half2 v = __floats2half2_rn(v0, v1);
        *reinterpret_cast<__half2*>(&g_xt[((size_t)b * LQ + l0 + l) * CIN + k0 + 2 * tx]) = v;
    }
}

// ---------------------------------------------------------------------------
// K1: mma.sync fp16 GEMM per batch.
// p rows (W_feat): C = (Wh + Wl) @ Xt^T, 16 chunks.
// d rows (W_dir):  C =  Wh @ Xt^T,        8 chunks (single pass).
// grid (4 m, 192 l, 8 b), 256 threads, 8 warps as 4(m) x 2(n), warp m32xn64
// 5-stage cp.async pipeline, chunk PAIRS, one barrier per pair
// ---------------------------------------------------------------------------
__global__ __launch_bounds__(256, 2)
void gemm_mma_kernel()
{
    extern __shared__ char smem[];            // NSTAGE * STAGE_BYTES
    const uint32_t su = smem_u32(smem);

    const int tid  = threadIdx.x;
    const int lane = tid & 31;
    const int w    = tid >> 5;
    const int wm   = w >> 1;                  // 0..3 -> 32 m rows each
    const int wn   = w & 1;                   // 0..1 -> 64 l cols each

    const int m0 = blockIdx.x * BM;           // 0,128,256,384 concat rows
    const int l0 = blockIdx.y * BN;
    const int b  = blockIdx.z;
    const size_t blbase = (size_t)b * LQ + l0;

    const int nkc = (m0 < COUT) ? NKC_P : NKC_D;   // d rows: single pass

    float acc[2][8][4];                       // 64 regs (warp m32 x n64)
#pragma unroll
    for (int i = 0; i < 2; i++)
#pragma unroll
        for (int j = 0; j < 8; j++)
#pragma unroll
            for (int q = 0; q < 4; q++) acc[i][j][q] = 0.f;

    const int f0 = tid * 2;                   // this thread's two 16B chunks
    auto load_stage = [&](int st, int kc) {
        const int seg  = kc >> 3;             // 0: Wh pass, 1: Wl pass
        const int koff = (kc & 7) * BK;
        const __half* Asrc = (seg == 0) ? g_whi : g_wlo;
        const uint32_t abase = su + st * STAGE_BYTES;
        const uint32_t bbase = abase + TILE_BYTES;
#pragma unroll
        for (int i = 0; i < 2; i++) {
            int f   = f0 + i;                 // 0..511
            int row = f >> 2;
            int ch  = f & 3;
            cp16(abase + row * ROWP + ch * 16,
                 Asrc + (size_t)(m0 + row) * CIN + koff + ch * 8);
            cp16(bbase + row * ROWP + ch * 16,
                 g_xt + (blbase + row) * CIN + koff + ch * 8);
        }
        CP_COMMIT();
    };

    // Prologue: fill 3 stages (chunks 0,1,2)
    load_stage(0, 0);
    load_stage(1, 1);
    load_stage(2, 2);

    const int lrow  = lane & 15;
    const int lhalf = lane >> 4;

    auto compute_chunk = [&](int st) {
        const uint32_t abase = su + st * STAGE_BYTES;
        const uint32_t bbase = abase + TILE_BYTES;
#pragma unroll
        for (int kk = 0; kk < 2; kk++) {       // two k16 steps in BK=32
            uint32_t a[2][4], bf[4][4];
#pragma unroll
            for (int i = 0; i < 2; i++)
                ldsm4(a[i], abase + (wm * 32 + i * 16 + lrow) * ROWP
                                  + (kk * 16 + lhalf * 8) * 2);
#pragma unroll
            for (int j = 0; j < 4; j++)
                ldsm4(bf[j], bbase + (wn * 64 + j * 16 + lrow) * ROWP
                                   + (kk * 16 + lhalf * 8) * 2);
#pragma unroll
            for (int i = 0; i < 2; i++)
#pragma unroll
                for (int j = 0; j < 4; j++) {
                    mma16816(acc[i][2 * j],     a[i], bf[j][0], bf[j][2]);
                    mma16816(acc[i][2 * j + 1], a[i], bf[j][1], bf[j][3]);
                }
        }
    };

    // Main loop: chunk-pairs, ONE barrier per pair, both prefetch loads issued
    // immediately after the barrier (their target stages held chunks kc-2 and
    // kc-1, both complete for all warps at this barrier; NSTAGE=5 keeps them
    // disjoint from stages kc, kc+1 still being read by skewed warps).
    int st = 0;                                // = kc % NSTAGE
    for (int kc = 0; kc < nkc; kc += 2) {
        CP_WAIT(2);                            // chunk kc arrived
        __syncthreads();                       // all warps done through chunk kc-1

        int st3 = st + 3; if (st3 >= NSTAGE) st3 -= NSTAGE;
        if (kc + 3 < nkc) load_stage(st3, kc + 3); else CP_COMMIT();
        int st4 = st + 4; if (st4 >= NSTAGE) st4 -= NSTAGE;
        if (kc + 4 < nkc) load_stage(st4, kc + 4); else CP_COMMIT();

        compute_chunk(st);

        CP_WAIT(3);                            // chunk kc+1 arrived
        int st1 = st + 1; if (st1 >= NSTAGE) st1 -= NSTAGE;
        compute_chunk(st1);

        st += 2; if (st >= NSTAGE) st -= NSTAGE;
    }

    // Epilogue: fragment -> g_p / g_d
    float* buf = (m0 < COUT) ? g_p : g_d;
#pragma unroll
    for (int i = 0; i < 2; i++) {
        int mrow0 = (m0 & (COUT - 1)) + wm * 32 + i * 16 + (lane >> 2);
#pragma unroll
        for (int j = 0; j < 8; j++) {
            int cg = l0 + wn * 64 + j * 8 + (lane & 3) * 2;
            float2 v0 = make_float2(acc[i][j][0], acc[i][j][1]);
            float2 v1 = make_float2(acc[i][j][2], acc[i][j][3]);
            *reinterpret_cast<float2*>(buf + ((size_t)b * COUT + mrow0) * LQ + cg)     = v0;
            *reinterpret_cast<float2*>(buf + ((size_t)b * COUT + mrow0 + 8) * LQ + cg) = v1;
        }
    }
}

// ---------------------------------------------------------------------------
// K0: zero stats accumulators (kept separate so GEMM remains launch #4 for ncu)
// ---------------------------------------------------------------------------
__global__ void zero_stats_kernel()
{
    int i = threadIdx.x;
    g_sum[i]   = 0.f;
    g_sumsq[i] = 0.f;
}

// ---------------------------------------------------------------------------
// K2: per-channel sum / sumsq of vector norms (float4 vectorized)
// ---------------------------------------------------------------------------
__global__ __launch_bounds__(256)
void stats_kernel()
{
    const int o = blockIdx.x;
    const int b = blockIdx.y;
    const float* base = g_p + ((size_t)b * COUT + o) * LQ;

    float s = 0.f, s2 = 0.f;
#pragma unroll
    for (int it = 0; it < NPTS / (256 * 4); it++) {
        int n = (it * 256 + threadIdx.x) * 4;
        float4 px = *reinterpret_cast<const float4*>(base + n);
        float4 py = *reinterpret_cast<const float4*>(base + NPTS + n);
        float4 pz = *reinterpret_cast<const float4*>(base + 2 * NPTS + n);
        float q0 = px.x * px.x + py.x * py.x + pz.x * pz.x;
        float q1 = px.y * px.y + py.y * py.y + pz.y * pz.y;
        float q2 = px.z * px.z + py.z * py.z + pz.z * pz.z;
        float q3 = px.w * px.w + py.w * py.w + pz.w * pz.w;
        s  += sqrtf(q0) + sqrtf(q1) + sqrtf(q2) + sqrtf(q3);
        s2 += q0 + q1 + q2 + q3;
    }
#pragma unroll
    for (int off = 16; off > 0; off >>= 1) {
        s  += __shfl_down_sync(0xffffffffu, s,  off);
        s2 += __shfl_down_sync(0xffffffffu, s2, off);
    }
    __shared__ float shs[8], shs2[8];
    int wid = threadIdx.x >> 5;
    int lid = threadIdx.x & 31;
    if (lid == 0) { shs[wid] = s; shs2[wid] = s2; }
    __syncthreads();
    if (threadIdx.x == 0) {
        float ts = 0.f, ts2 = 0.f;
#pragma unroll
        for (int w = 0; w < 8; w++) { ts += shs[w]; ts2 += shs2[w]; }
        atomicAdd(&g_sum[o],   ts);
        atomicAdd(&g_sumsq[o], ts2);
    }
}

// ---------------------------------------------------------------------------
// K3: finalize BN affine per channel
// ---------------------------------------------------------------------------
__global__ void finalize_kernel(const float* __restrict__ gamma,
                                const float* __restrict__ beta)
{
    int o = threadIdx.x;
    const float inv = 1.0f / (float)(BQ * NPTS);
    float mean = g_sum[o] * inv;
    float var  = g_sumsq[o] * inv - mean * mean;
    float rstd = rsqrtf(var + 1e-5f);
    float a = rstd * gamma[o];
    g_bn_a[o] = a;
    g_bn_b[o] = beta[o] - mean * a;
}

// ---------------------------------------------------------------------------
// K4: BN rescale + VN LeakyReLU (float4 vectorized: 4 points per thread)
// ---------------------------------------------------------------------------
__global__ __launch_bounds__(256)
void epilogue_kernel(float* __restrict__ out)
{
    const int n = (blockIdx.x * 256 + threadIdx.x) * 4;
    const int o = blockIdx.y;
    const int b = blockIdx.z;
    const size_t base = ((size_t)b * COUT + o) * LQ + n;

    float4 px = *reinterpret_cast<const float4*>(g_p + base);
    float4 py = *reinterpret_cast<const float4*>(g_p + base + NPTS);
    float4 pz = *reinterpret_cast<const float4*>(g_p + base + 2 * NPTS);
    float4 dx = *reinterpret_cast<const float4*>(g_d + base);
    float4 dy = *reinterpret_cast<const float4*>(g_d + base + NPTS);
    float4 dz = *reinterpret_cast<const float4*>(g_d + base + 2 * NPTS);

    const float bna = __ldg(&g_bn_a[o]);
    const float bnb = __ldg(&g_bn_b[o]);

    float opx[4], opy[4], opz[4];
    const float* pxs = &px.x; const float* pys = &py.x; const float* pzs = &pz.x;
    const float* dxs = &dx.x; const float* dys = &dy.x; const float* dzs = &dz.x;
#pragma unroll
    for (int q = 0; q < 4; q++) {
        float ax = pxs[q], ay = pys[q], az = pzs[q];
        float ex = dxs[q], ey = dys[q], ez = dzs[q];
        float nrm = sqrtf(ax * ax + ay * ay + az * az);
        float f = bna + bnb / nrm;
        ax *= f; ay *= f; az *= f;
        float dot = ax * ex + ay * ey + az * ez;
        float dsq = ex * ex + ey * ey + ez * ez;
        if (dot < 0.f) {
            float c = 0.8f * dot / (dsq + 1e-6f);
            ax -= c * ex; ay -= c * ey; az -= c * ez;
        }
        opx[q] = ax; opy[q] = ay; opz[q] = az;
    }
    *reinterpret_cast<float4*>(out + base)            = make_float4(opx[0], opx[1], opx[2], opx[3]);
    *reinterpret_cast<float4*>(out + base + NPTS)     = make_float4(opy[0], opy[1], opy[2], opy[3]);
    *reinterpret_cast<float4*>(out + base + 2 * NPTS) = make_float4(opz[0], opz[1], opz[2], opz[3]);
}

// ---------------------------------------------------------------------------
extern "C" void kernel_launch(void* const* d_in, const int* in_sizes, int n_in,
                              void* d_out, int out_size)
{
    const float* x     = (const float*)d_in[0];
    const float* Wf    = (const float*)d_in[1];
    const float* Wd    = (const float*)d_in[2];
    const float* gamma = (const float*)d_in[3];
    const float* beta  = (const float*)d_in[4];
    float* out = (float*)d_out;

    (void)cudaFuncSetAttribute(gemm_mma_kernel,
                               cudaFuncAttributeMaxDynamicSharedMemorySize, SMEM_TOTAL);

    convert_w_kernel<<<MTOT, CIN>>>(Wf, Wd);

    dim3 tgrid(LQ / 32, CIN / 64, BQ);
    transpose_split_kernel<<<tgrid, dim3(32, 8)>>>(x);

    zero_stats_kernel<<<1, COUT>>>();          // GEMM stays launch #4 (ncu target)

    dim3 ggrid(MTOT / BM, LQ / BN, BQ);        // (4, 192, 8)
    gemm_mma_kernel<<<ggrid, 256, SMEM_TOTAL>>>();

    stats_kernel<<<dim3(COUT, BQ), 256>>>();
    finalize_kernel<<<1, COUT>>>(gamma, beta);
    epilogue_kernel<<<dim3(NPTS / 1024, COUT, BQ), 256>>>(out);
}

// round 16
// speedup vs baseline: 2.0325x; 1.0004x over previous
#include <cuda_runtime.h>
#include <cuda_fp16.h>
#include <math.h>
#include <stdint.h>

// Problem constants
#define BQ    8
#define CIN   256
#define COUT  256
#define NPTS  8192
#define LQ    (3 * NPTS)      // 24576 columns per (batch) GEMM
#define MTOT  (2 * COUT)      // 512 rows: [W_feat; W_dir]

// GEMM tiling: fused hi/lo chunks
#define BM 128
#define BN 128
#define BK 32
#define NKC 8                 // 8 chunks cover K=256 once; p fuses Wh+Wl per chunk
#define NSTAGE 3

// SMEM: rows of 64B data padded to 80B pitch (conflict-free ldmatrix)
// Stage: A 256 rows (hi 0-127, lo 128-255) + B 128 rows
#define ROWP 80
#define A_BYTES (256 * ROWP)              // 20480
#define B_BYTES (128 * ROWP)              // 10240
#define STAGE_BYTES (A_BYTES + B_BYTES)   // 30720
#define SMEM_TOTAL (NSTAGE * STAGE_BYTES) // 92160 (x2 CTA = 184KB <= 227KB)

// ---------------------------------------------------------------------------
// Static device scratch (no runtime allocation)
// ---------------------------------------------------------------------------
__device__ float g_p[(size_t)BQ * COUT * LQ];   // 192 MiB
__device__ float g_d[(size_t)BQ * COUT * LQ];   // 192 MiB
__device__ __half g_xt[(size_t)BQ * LQ * CIN];  // transposed [b, l, k] fp16
__device__ __half g_whi[MTOT * CIN];
__device__ __half g_wlo[MTOT * CIN];
__device__ float g_sum[COUT];
__device__ float g_sumsq[COUT];
__device__ float g_bn_a[COUT];
__device__ float g_bn_b[COUT];

// ---------------------------------------------------------------------------
// PTX helpers (sm_80-era: valid for plain sm_103 target)
// ---------------------------------------------------------------------------
__device__ __forceinline__ uint32_t smem_u32(const void* p) {
    uint32_t a;
    asm("{ .reg .u64 t; cvta.to.shared.u64 t, %1; cvt.u32.u64 %0, t; }" : "=r"(a) : "l"(p));
    return a;
}

__device__ __forceinline__ void cp16(uint32_t dst, const void* src) {
    asm volatile("cp.async.cg.shared.global [%0], [%1], 16;" :: "r"(dst), "l"(src) : "memory");
}
#define CP_COMMIT() asm volatile("cp.async.commit_group;" ::: "memory")
#define CP_WAIT(n)  asm volatile("cp.async.wait_group %0;" :: "n"(n) : "memory")

__device__ __forceinline__ void ldsm4(uint32_t* r, uint32_t addr) {
    asm volatile("ldmatrix.sync.aligned.m8n8.x4.shared.b16 {%0,%1,%2,%3}, [%4];"
                 : "=r"(r[0]), "=r"(r[1]), "=r"(r[2]), "=r"(r[3]) : "r"(addr));
}

__device__ __forceinline__ void mma16816(float* c, const uint32_t* a,
                                         uint32_t b0, uint32_t b1) {
    asm volatile(
        "mma.sync.aligned.m16n8k16.row.col.f32.f16.f16.f32 "
        "{%0,%1,%2,%3}, {%4,%5,%6,%7}, {%8,%9}, {%0,%1,%2,%3};"
        : "+f"(c[0]), "+f"(c[1]), "+f"(c[2]), "+f"(c[3])
        : "r"(a[0]), "r"(a[1]), "r"(a[2]), "r"(a[3]), "r"(b0), "r"(b1));
}

// ---------------------------------------------------------------------------
// K_a: W -> concatenated fp16 hi/lo [512, 256]
// ---------------------------------------------------------------------------
__global__ void convert_w_kernel(const float* __restrict__ Wf, const float* __restrict__ Wd)
{
    int row = blockIdx.x;
    int col = threadIdx.x;
    float v = (row < COUT) ? Wf[row * CIN + col] : Wd[(row - COUT) * CIN + col];
    __half hi = __float2half_rn(v);
    float r = v - __half2float(hi);
    g_whi[row * CIN + col] = hi;
    g_wlo[row * CIN + col] = __float2half_rn(r);
}

// ---------------------------------------------------------------------------
// K_b: x [b, k, l] fp32 -> Xt [b, l, k] fp16 (transpose + round)
// ---------------------------------------------------------------------------
__global__ __launch_bounds__(256)
void transpose_split_kernel(const float* __restrict__ x)
{
    __shared__ float s[32][65];               // [l][k], pitch 65 words
    const int b  = blockIdx.z;
    const int k0 = blockIdx.y * 64;
    const int l0 = blockIdx.x * 32;
    const int tx = threadIdx.x, ty = threadIdx.y;   // 32 x 8

    const float* xb = x + ((size_t)b * CIN + k0) * LQ + l0;
#pragma unroll
    for (int i = 0; i < 8; i++) {
        int k = ty + i * 8;
        s[tx][k] = xb[(size_t)k * LQ + tx];   // coalesced gmem; conflict-free smem
    }
    __syncthreads();
#pragma unroll
    for (int i = 0; i < 4; i++) {
        int l = ty + i * 8;
        float v0 = s[l][2 * tx];              // scalar reads: 4B-aligned always
        float v1 = s[l][2 * tx + 1];
        __half2 v = __floats2half2_rn(v0, v1);
        *reinterpret_cast<__half2*>(&g_xt[((size_t)b * LQ + l0 + l) * CIN + k0 + 2 * tx]) = v;
    }
}

// ---------------------------------------------------------------------------
// K1: mma.sync fp16 GEMM per batch, fused-split chunks.
// p rows (W_feat): acc += Wh*X + Wl*X per chunk (B fragments reused).
// d rows (W_dir):  acc += Wh*X only.
// grid (4 m, 192 l, 8 b), 256 threads, 8 warps as 4(m) x 2(n), warp m32xn64
// 3-stage cp.async pipeline, one barrier per chunk (2048 tensor-cyc each)
// ---------------------------------------------------------------------------
__global__ __launch_bounds__(256, 2)
void gemm_mma_kernel()
{
    extern __shared__ char smem[];            // NSTAGE * STAGE_BYTES
    const uint32_t su = smem_u32(smem);

    const int tid  = threadIdx.x;
    const int lane = tid & 31;
    const int w    = tid >> 5;
    const int wm   = w >> 1;                  // 0..3 -> 32 m rows each
    const int wn   = w & 1;                   // 0..1 -> 64 l cols each

    const int m0 = blockIdx.x * BM;           // 0,128,256,384 concat rows
    const int l0 = blockIdx.y * BN;
    const int b  = blockIdx.z;
    const size_t blbase = (size_t)b * LQ + l0;

    const bool two_pass = (m0 < COUT);        // p rows fuse Wh+Wl; d rows Wh only

    float acc[2][8][4];                       // 64 regs (warp m32 x n64)
#pragma unroll
    for (int i = 0; i < 2; i++)
#pragma unroll
        for (int j = 0; j < 8; j++)
#pragma unroll
            for (int q = 0; q < 4; q++) acc[i][j][q] = 0.f;

    // Per stage: A-hi 512 cp16 slots + A-lo 512 (p only) + B 512; 256 threads
    const int f0 = tid * 2;
    auto load_stage = [&](int st, int kc) {
        const int koff = kc * BK;
        const uint32_t abase = su + st * STAGE_BYTES;
        const uint32_t bbase = abase + A_BYTES;
#pragma unroll
        for (int i = 0; i < 2; i++) {
            int f   = f0 + i;                 // 0..511
            int row = f >> 2;
            int ch  = f & 3;
            cp16(abase + row * ROWP + ch * 16,
                 g_whi + (size_t)(m0 + row) * CIN + koff + ch * 8);
            if (two_pass)
                cp16(abase + (128 + row) * ROWP + ch * 16,
                     g_wlo + (size_t)(m0 + row) * CIN + koff + ch * 8);
            cp16(bbase + row * ROWP + ch * 16,
                 g_xt + (blbase + row) * CIN + koff + ch * 8);
        }
        CP_COMMIT();
    };

    // Prologue: fill 2 stages (chunks 0,1)
    load_stage(0, 0);
    load_stage(1, 1);

    const int lrow  = lane & 15;
    const int lhalf = lane >> 4;

    int st = 0;                                // = kc % NSTAGE
    for (int kc = 0; kc < NKC; kc++) {
        CP_WAIT(1);                            // chunk kc arrived (exact: 1 group/chunk)
        __syncthreads();                       // all warps done with stage kc-1
        // Load after barrier: target stage (kc+2)%3 held chunk kc-1 (complete).
        int st2 = st + 2; if (st2 >= NSTAGE) st2 -= NSTAGE;
        if (kc + 2 < NKC) load_stage(st2, kc + 2); else CP_COMMIT();

        const uint32_t abase = su + st * STAGE_BYTES;
        const uint32_t bbase = abase + A_BYTES;

#pragma unroll
        for (int kk = 0; kk < 2; kk++) {       // two k16 steps in BK=32
            uint32_t ah[2][4], al[2][4], bf[4][4];
#pragma unroll
            for (int j = 0; j < 4; j++)
                ldsm4(bf[j], bbase + (wn * 64 + j * 16 + lrow) * ROWP
                                   + (kk * 16 + lhalf * 8) * 2);
#pragma unroll
            for (int i = 0; i < 2; i++)
                ldsm4(ah[i], abase + (wm * 32 + i * 16 + lrow) * ROWP
                                   + (kk * 16 + lhalf * 8) * 2);
#pragma unroll
            for (int i = 0; i < 2; i++)
#pragma unroll
                for (int j = 0; j < 4; j++) {
                    mma16816(acc[i][2 * j],     ah[i], bf[j][0], bf[j][2]);
                    mma16816(acc[i][2 * j + 1], ah[i], bf[j][1], bf[j][3]);
                }
            if (two_pass) {
#pragma unroll
                for (int i = 0; i < 2; i++)
                    ldsm4(al[i], abase + (128 + wm * 32 + i * 16 + lrow) * ROWP
                                       + (kk * 16 + lhalf * 8) * 2);
#pragma unroll
                for (int i = 0; i < 2; i++)
#pragma unroll
                    for (int j = 0; j < 4; j++) {
                        mma16816(acc[i][2 * j],     al[i], bf[j][0], bf[j][2]);
                        mma16816(acc[i][2 * j + 1], al[i], bf[j][1], bf[j][3]);
                    }
            }
        }
        st++; if (st >= NSTAGE) st -= NSTAGE;
    }

    // Epilogue: fragment -> g_p / g_d
    float* buf = two_pass ? g_p : g_d;
#pragma unroll
    for (int i = 0; i < 2; i++) {
        int mrow0 = (m0 & (COUT - 1)) + wm * 32 + i * 16 + (lane >> 2);
#pragma unroll
        for (int j = 0; j < 8; j++) {
            int cg = l0 + wn * 64 + j * 8 + (lane & 3) * 2;
            float2 v0 = make_float2(acc[i][j][0], acc[i][j][1]);
            float2 v1 = make_float2(acc[i][j][2], acc[i][j][3]);
            *reinterpret_cast<float2*>(buf + ((size_t)b * COUT + mrow0) * LQ + cg)     = v0;
            *reinterpret_cast<float2*>(buf + ((size_t)b * COUT + mrow0 + 8) * LQ + cg) = v1;
        }
    }
}

// ---------------------------------------------------------------------------
// K0: zero stats accumulators (kept separate so GEMM remains launch #4 for ncu)
// ---------------------------------------------------------------------------
__global__ void zero_stats_kernel()
{
    int i = threadIdx.x;
    g_sum[i]   = 0.f;
    g_sumsq[i] = 0.f;
}

// ---------------------------------------------------------------------------
// K2: per-channel sum / sumsq of vector norms (float4 vectorized)
// ---------------------------------------------------------------------------
__global__ __launch_bounds__(256)
void stats_kernel()
{
    const int o = blockIdx.x;
    const int b = blockIdx.y;
    const float* base = g_p + ((size_t)b * COUT + o) * LQ;

    float s = 0.f, s2 = 0.f;
#pragma unroll
    for (int it = 0; it < NPTS / (256 * 4); it++) {
        int n = (it * 256 + threadIdx.x) * 4;
        float4 px = *reinterpret_cast<const float4*>(base + n);
        float4 py = *reinterpret_cast<const float4*>(base + NPTS + n);
        float4 pz = *reinterpret_cast<const float4*>(base + 2 * NPTS + n);
        float q0 = px.x * px.x + py.x * py.x + pz.x * pz.x;
        float q1 = px.y * px.y + py.y * py.y + pz.y * pz.y;
        float q2 = px.z * px.z + py.z * py.z + pz.z * pz.z;
        float q3 = px.w * px.w + py.w * py.w + pz.w * pz.w;
        s  += sqrtf(q0) + sqrtf(q1) + sqrtf(q2) + sqrtf(q3);
        s2 += q0 + q1 + q2 + q3;
    }
#pragma unroll
    for (int off = 16; off > 0; off >>= 1) {
        s  += __shfl_down_sync(0xffffffffu, s,  off);
        s2 += __shfl_down_sync(0xffffffffu, s2, off);
    }
    __shared__ float shs[8], shs2[8];
    int wid = threadIdx.x >> 5;
    int lid = threadIdx.x & 31;
    if (lid == 0) { shs[wid] = s; shs2[wid] = s2; }
    __syncthreads();
    if (threadIdx.x == 0) {
        float ts = 0.f, ts2 = 0.f;
#pragma unroll
        for (int w = 0; w < 8; w++) { ts += shs[w]; ts2 += shs2[w]; }
        atomicAdd(&g_sum[o],   ts);
        atomicAdd(&g_sumsq[o], ts2);
    }
}

// ---------------------------------------------------------------------------
// K3: finalize BN affine per channel
// ---------------------------------------------------------------------------
__global__ void finalize_kernel(const float* __restrict__ gamma,
                                const float* __restrict__ beta)
{
    int o = threadIdx.x;
    const float inv = 1.0f / (float)(BQ * NPTS);
    float mean = g_sum[o] * inv;
    float var  = g_sumsq[o] * inv - mean * mean;
    float rstd = rsqrtf(var + 1e-5f);
    float a = rstd * gamma[o];
    g_bn_a[o] = a;
    g_bn_b[o] = beta[o] - mean * a;
}

// ---------------------------------------------------------------------------
// K4: BN rescale + VN LeakyReLU (float4 vectorized: 4 points per thread)
// ---------------------------------------------------------------------------
__global__ __launch_bounds__(256)
void epilogue_kernel(float* __restrict__ out)
{
    const int n = (blockIdx.x * 256 + threadIdx.x) * 4;
    const int o = blockIdx.y;
    const int b = blockIdx.z;
    const size_t base = ((size_t)b * COUT + o) * LQ + n;

    float4 px = *reinterpret_cast<const float4*>(g_p + base);
    float4 py = *reinterpret_cast<const float4*>(g_p + base + NPTS);
    float4 pz = *reinterpret_cast<const float4*>(g_p + base + 2 * NPTS);
    float4 dx = *reinterpret_cast<const float4*>(g_d + base);
    float4 dy = *reinterpret_cast<const float4*>(g_d + base + NPTS);
    float4 dz = *reinterpret_cast<const float4*>(g_d + base + 2 * NPTS);

    const float bna = __ldg(&g_bn_a[o]);
    const float bnb = __ldg(&g_bn_b[o]);

    float opx[4], opy[4], opz[4];
    const float* pxs = &px.x; const float* pys = &py.x; const float* pzs = &pz.x;
    const float* dxs = &dx.x; const float* dys = &dy.x; const float* dzs = &dz.x;
#pragma unroll
    for (int q = 0; q < 4; q++) {
        float ax = pxs[q], ay = pys[q], az = pzs[q];
        float ex = dxs[q], ey = dys[q], ez = dzs[q];
        float nrm = sqrtf(ax * ax + ay * ay + az * az);
        float f = bna + bnb / nrm;
        ax *= f; ay *= f; az *= f;
        float dot = ax * ex + ay * ey + az * ez;
        float dsq = ex * ex + ey * ey + ez * ez;
        if (dot < 0.f) {
            float c = 0.8f * dot / (dsq + 1e-6f);
            ax -= c * ex; ay -= c * ey; az -= c * ez;
        }
        opx[q] = ax; opy[q] = ay; opz[q] = az;
    }
    *reinterpret_cast<float4*>(out + base)            = make_float4(opx[0], opx[1], opx[2], opx[3]);
    *reinterpret_cast<float4*>(out + base + NPTS)     = make_float4(opy[0], opy[1], opy[2], opy[3]);
    *reinterpret_cast<float4*>(out + base + 2 * NPTS) = make_float4(opz[0], opz[1], opz[2], opz[3]);
}

// ---------------------------------------------------------------------------
extern "C" void kernel_launch(void* const* d_in, const int* in_sizes, int n_in,
                              void* d_out, int out_size)
{
    const float* x     = (const float*)d_in[0];
    const float* Wf    = (const float*)d_in[1];
    const float* Wd    = (const float*)d_in[2];
    const float* gamma = (const float*)d_in[3];
    const float* beta  = (const float*)d_in[4];
    float* out = (float*)d_out;

    (void)cudaFuncSetAttribute(gemm_mma_kernel,
                               cudaFuncAttributeMaxDynamicSharedMemorySize, SMEM_TOTAL);

    convert_w_kernel<<<MTOT, CIN>>>(Wf, Wd);

    dim3 tgrid(LQ / 32, CIN / 64, BQ);
    transpose_split_kernel<<<tgrid, dim3(32, 8)>>>(x);

    zero_stats_kernel<<<1, COUT>>>();          // GEMM stays launch #4 (ncu target)

    dim3 ggrid(MTOT / BM, LQ / BN, BQ);        // (4, 192, 8)
    gemm_mma_kernel<<<ggrid, 256, SMEM_TOTAL>>>();

    stats_kernel<<<dim3(COUT, BQ), 256>>>();
    finalize_kernel<<<1, COUT>>>(gamma, beta);
    epilogue_kernel<<<dim3(NPTS / 1024, COUT, BQ), 256>>>(out);
}

// round 17
// speedup vs baseline: 2.1595x; 1.0624x over previous
#include <cuda_runtime.h>
#include <cuda_fp16.h>
#include <math.h>
#include <stdint.h>

// Problem constants
#define BQ    8
#define CIN   256
#define COUT  256
#define NPTS  8192
#define LQ    (3 * NPTS)      // 24576 columns per (batch) GEMM
#define MTOT  (2 * COUT)      // 512 rows: [W_feat; W_dir]

// GEMM tiling: fused hi/lo chunks (R16 structure, kept)
#define BM 128
#define BN 128
#define BK 32
#define NKC 8
#define NSTAGE 3

#define ROWP 80
#define A_BYTES (256 * ROWP)              // 20480
#define B_BYTES (128 * ROWP)              // 10240
#define STAGE_BYTES (A_BYTES + B_BYTES)   // 30720
#define SMEM_TOTAL (NSTAGE * STAGE_BYTES) // 92160 (x2 CTA = 184KB <= 227KB)

// ---------------------------------------------------------------------------
// Static device scratch (no runtime allocation) -- p/d now fp16 (100 MiB each)
// ---------------------------------------------------------------------------
__device__ __half g_p[(size_t)BQ * COUT * LQ];
__device__ __half g_d[(size_t)BQ * COUT * LQ];
__device__ __half g_xt[(size_t)BQ * LQ * CIN];  // transposed [b, l, k] fp16
__device__ __half g_whi[MTOT * CIN];
__device__ __half g_wlo[MTOT * CIN];
__device__ float g_sum[COUT];
__device__ float g_sumsq[COUT];
__device__ float g_bn_a[COUT];
__device__ float g_bn_b[COUT];

// ---------------------------------------------------------------------------
// PTX helpers (sm_80-era: valid for plain sm_103 target)
// ---------------------------------------------------------------------------
__device__ __forceinline__ uint32_t smem_u32(const void* p) {
    uint32_t a;
    asm("{ .reg .u64 t; cvta.to.shared.u64 t, %1; cvt.u32.u64 %0, t; }" : "=r"(a) : "l"(p));
    return a;
}

__device__ __forceinline__ void cp16(uint32_t dst, const void* src) {
    asm volatile("cp.async.cg.shared.global [%0], [%1], 16;" :: "r"(dst), "l"(src) : "memory");
}
#define CP_COMMIT() asm volatile("cp.async.commit_group;" ::: "memory")
#define CP_WAIT(n)  asm volatile("cp.async.wait_group %0;" :: "n"(n) : "memory")

__device__ __forceinline__ void ldsm4(uint32_t* r, uint32_t addr) {
    asm volatile("ldmatrix.sync.aligned.m8n8.x4.shared.b16 {%0,%1,%2,%3}, [%4];"
                 : "=r"(r[0]), "=r"(r[1]), "=r"(r[2]), "=r"(r[3]) : "r"(addr));
}

__device__ __forceinline__ void mma16816(float* c, const uint32_t* a,
                                         uint32_t b0, uint32_t b1) {
    asm volatile(
        "mma.sync.aligned.m16n8k16.row.col.f32.f16.f16.f32 "
        "{%0,%1,%2,%3}, {%4,%5,%6,%7}, {%8,%9}, {%0,%1,%2,%3};"
        : "+f"(c[0]), "+f"(c[1]), "+f"(c[2]), "+f"(c[3])
        : "r"(a[0]), "r"(a[1]), "r"(a[2]), "r"(a[3]), "r"(b0), "r"(b1));
}

// ---------------------------------------------------------------------------
// K_a: W -> concatenated fp16 hi/lo [512, 256]
// ---------------------------------------------------------------------------
__global__ void convert_w_kernel(const float* __restrict__ Wf, const float* __restrict__ Wd)
{
    int row = blockIdx.x;
    int col = threadIdx.x;
    float v = (row < COUT) ? Wf[row * CIN + col] : Wd[(row - COUT) * CIN + col];
    __half hi = __float2half_rn(v);
    float r = v - __half2float(hi);
    g_whi[row * CIN + col] = hi;
    g_wlo[row * CIN + col] = __float2half_rn(r);
}

// ---------------------------------------------------------------------------
// K_b: x [b, k, l] fp32 -> Xt [b, l, k] fp16 (transpose + round)
// ---------------------------------------------------------------------------
__global__ __launch_bounds__(256)
void transpose_split_kernel(const float* __restrict__ x)
{
    __shared__ float s[32][65];               // [l][k], pitch 65 words
    const int b  = blockIdx.z;
    const int k0 = blockIdx.y * 64;
    const int l0 = blockIdx.x * 32;
    const int tx = threadIdx.x, ty = threadIdx.y;   // 32 x 8

    const float* xb = x + ((size_t)b * CIN + k0) * LQ + l0;
#pragma unroll
    for (int i = 0; i < 8; i++) {
        int k = ty + i * 8;
        s[tx][k] = xb[(size_t)k * LQ + tx];
    }
    __syncthreads();
#pragma unroll
    for (int i = 0; i < 4; i++) {
        int l = ty + i * 8;
        float v0 = s[l][2 * tx];              // scalar reads: 4B-aligned always
        float v1 = s[l][2 * tx + 1];
        __half2 v = __floats2half2_rn(v0, v1);
        *reinterpret_cast<__half2*>(&g_xt[((size_t)b * LQ + l0 + l) * CIN + k0 + 2 * tx]) = v;
    }
}

// ---------------------------------------------------------------------------
// K1: mma.sync fp16 GEMM per batch, fused-split chunks (R16 structure).
// p rows (W_feat): acc += Wh*X + Wl*X per chunk (B fragments reused).
// d rows (W_dir):  acc += Wh*X only.
// Output stored as fp16.
// ---------------------------------------------------------------------------
__global__ __launch_bounds__(256, 2)
void gemm_mma_kernel()
{
    extern __shared__ char smem[];            // NSTAGE * STAGE_BYTES
    const uint32_t su = smem_u32(smem);

    const int tid  = threadIdx.x;
    const int lane = tid & 31;
    const int w    = tid >> 5;
    const int wm   = w >> 1;                  // 0..3 -> 32 m rows each
    const int wn   = w & 1;                   // 0..1 -> 64 l cols each

    const int m0 = blockIdx.x * BM;           // 0,128,256,384 concat rows
    const int l0 = blockIdx.y * BN;
    const int b  = blockIdx.z;
    const size_t blbase = (size_t)b * LQ + l0;

    const bool two_pass = (m0 < COUT);        // p rows fuse Wh+Wl; d rows Wh only

    float acc[2][8][4];                       // 64 regs (warp m32 x n64)
#pragma unroll
    for (int i = 0; i < 2; i++)
#pragma unroll
        for (int j = 0; j < 8; j++)
#pragma unroll
            for (int q = 0; q < 4; q++) acc[i][j][q] = 0.f;

    const int f0 = tid * 2;
    auto load_stage = [&](int st, int kc) {
        const int koff = kc * BK;
        const uint32_t abase = su + st * STAGE_BYTES;
        const uint32_t bbase = abase + A_BYTES;
#pragma unroll
        for (int i = 0; i < 2; i++) {
            int f   = f0 + i;                 // 0..511
            int row = f >> 2;
            int ch  = f & 3;
            cp16(abase + row * ROWP + ch * 16,
                 g_whi + (size_t)(m0 + row) * CIN + koff + ch * 8);
            if (two_pass)
                cp16(abase + (128 + row) * ROWP + ch * 16,
                     g_wlo + (size_t)(m0 + row) * CIN + koff + ch * 8);
            cp16(bbase + row * ROWP + ch * 16,
                 g_xt + (blbase + row) * CIN + koff + ch * 8);
        }
        CP_COMMIT();
    };

    // Prologue: fill 2 stages (chunks 0,1)
    load_stage(0, 0);
    load_stage(1, 1);

    const int lrow  = lane & 15;
    const int lhalf = lane >> 4;

    int st = 0;                                // = kc % NSTAGE
    for (int kc = 0; kc < NKC; kc++) {
        CP_WAIT(1);                            // chunk kc arrived
        __syncthreads();                       // all warps done with stage kc-1
        int st2 = st + 2; if (st2 >= NSTAGE) st2 -= NSTAGE;
        if (kc + 2 < NKC) load_stage(st2, kc + 2); else CP_COMMIT();

        const uint32_t abase = su + st * STAGE_BYTES;
        const uint32_t bbase = abase + A_BYTES;

#pragma unroll
        for (int kk = 0; kk < 2; kk++) {       // two k16 steps in BK=32
            uint32_t ah[2][4], al[2][4], bf[4][4];
#pragma unroll
            for (int j = 0; j < 4; j++)
                ldsm4(bf[j], bbase + (wn * 64 + j * 16 + lrow) * ROWP
                                   + (kk * 16 + lhalf * 8) * 2);
#pragma unroll
            for (int i = 0; i < 2; i++)
                ldsm4(ah[i], abase + (wm * 32 + i * 16 + lrow) * ROWP
                                   + (kk * 16 + lhalf * 8) * 2);
#pragma unroll
            for (int i = 0; i < 2; i++)
#pragma unroll
                for (int j = 0; j < 4; j++) {
                    mma16816(acc[i][2 * j],     ah[i], bf[j][0], bf[j][2]);
                    mma16816(acc[i][2 * j + 1], ah[i], bf[j][1], bf[j][3]);
                }
            if (two_pass) {
#pragma unroll
                for (int i = 0; i < 2; i++)
                    ldsm4(al[i], abase + (128 + wm * 32 + i * 16 + lrow) * ROWP
                                       + (kk * 16 + lhalf * 8) * 2);
#pragma unroll
                for (int i = 0; i < 2; i++)
#pragma unroll
                    for (int j = 0; j < 4; j++) {
                        mma16816(acc[i][2 * j],     al[i], bf[j][0], bf[j][2]);
                        mma16816(acc[i][2 * j + 1], al[i], bf[j][1], bf[j][3]);
                    }
            }
        }
        st++; if (st >= NSTAGE) st -= NSTAGE;
    }

    // Epilogue: fragment -> fp16 g_p / g_d
    __half* buf = two_pass ? g_p : g_d;
#pragma unroll
    for (int i = 0; i < 2; i++) {
        int mrow0 = (m0 & (COUT - 1)) + wm * 32 + i * 16 + (lane >> 2);
#pragma unroll
        for (int j = 0; j < 8; j++) {
            int cg = l0 + wn * 64 + j * 8 + (lane & 3) * 2;   // even -> half2 aligned
            __half2 v0 = __floats2half2_rn(acc[i][j][0], acc[i][j][1]);
            __half2 v1 = __floats2half2_rn(acc[i][j][2], acc[i][j][3]);
            *reinterpret_cast<__half2*>(buf + ((size_t)b * COUT + mrow0) * LQ + cg)     = v0;
            *reinterpret_cast<__half2*>(buf + ((size_t)b * COUT + mrow0 + 8) * LQ + cg) = v1;
        }
    }
}

// ---------------------------------------------------------------------------
// K0: zero stats accumulators
// ---------------------------------------------------------------------------
__global__ void zero_stats_kernel()
{
    int i = threadIdx.x;
    g_sum[i]   = 0.f;
    g_sumsq[i] = 0.f;
}

// ---------------------------------------------------------------------------
// K2: per-channel sum / sumsq of vector norms (uint4 = 8 halves per load)
// grid: (COUT, BQ); block 256; 8192 pts = 256 thr x 8 x 4 iters
// ---------------------------------------------------------------------------
__global__ __launch_bounds__(256)
void stats_kernel()
{
    const int o = blockIdx.x;
    const int b = blockIdx.y;
    const __half* base = g_p + ((size_t)b * COUT + o) * LQ;

    float s = 0.f, s2 = 0.f;
#pragma unroll
    for (int it = 0; it < NPTS / (256 * 8); it++) {
        int n = (it * 256 + threadIdx.x) * 8;
        uint4 ux = *reinterpret_cast<const uint4*>(base + n);
        uint4 uy = *reinterpret_cast<const uint4*>(base + NPTS + n);
        uint4 uz = *reinterpret_cast<const uint4*>(base + 2 * NPTS + n);
        const uint32_t* wx = &ux.x;
        const uint32_t* wy = &uy.x;
        const uint32_t* wz = &uz.x;
#pragma unroll
        for (int q = 0; q < 4; q++) {
            float2 fx = __half22float2(*reinterpret_cast<const __half2*>(&wx[q]));
            float2 fy = __half22float2(*reinterpret_cast<const __half2*>(&wy[q]));
            float2 fz = __half22float2(*reinterpret_cast<const __half2*>(&wz[q]));
            float q0 = fx.x * fx.x + fy.x * fy.x + fz.x * fz.x;
            float q1 = fx.y * fx.y + fy.y * fy.y + fz.y * fz.y;
            s  += sqrtf(q0) + sqrtf(q1);
            s2 += q0 + q1;
        }
    }
#pragma unroll
    for (int off = 16; off > 0; off >>= 1) {
        s  += __shfl_down_sync(0xffffffffu, s,  off);
        s2 += __shfl_down_sync(0xffffffffu, s2, off);
    }
    __shared__ float shs[8], shs2[8];
    int wid = threadIdx.x >> 5;
    int lid = threadIdx.x & 31;
    if (lid == 0) { shs[wid] = s; shs2[wid] = s2; }
    __syncthreads();
    if (threadIdx.x == 0) {
        float ts = 0.f, ts2 = 0.f;
#pragma unroll
        for (int w = 0; w < 8; w++) { ts += shs[w]; ts2 += shs2[w]; }
        atomicAdd(&g_sum[o],   ts);
        atomicAdd(&g_sumsq[o], ts2);
    }
}

// ---------------------------------------------------------------------------
// K3: finalize BN affine per channel
// ---------------------------------------------------------------------------
__global__ void finalize_kernel(const float* __restrict__ gamma,
                                const float* __restrict__ beta)
{
    int o = threadIdx.x;
    const float inv = 1.0f / (float)(BQ * NPTS);
    float mean = g_sum[o] * inv;
    float var  = g_sumsq[o] * inv - mean * mean;
    float rstd = rsqrtf(var + 1e-5f);
    float a = rstd * gamma[o];
    g_bn_a[o] = a;
    g_bn_b[o] = beta[o] - mean * a;
}

// ---------------------------------------------------------------------------
// K4: BN rescale + VN LeakyReLU (8 points per thread from fp16 scratch)
// grid: (NPTS/2048, COUT, BQ); block 256
// ---------------------------------------------------------------------------
__global__ __launch_bounds__(256)
void epilogue_kernel(float* __restrict__ out)
{
    const int n = (blockIdx.x * 256 + threadIdx.x) * 8;
    const int o = blockIdx.y;
    const int b = blockIdx.z;
    const size_t base = ((size_t)b * COUT + o) * LQ + n;

    uint4 upx = *reinterpret_cast<const uint4*>(g_p + base);
    uint4 upy = *reinterpret_cast<const uint4*>(g_p + base + NPTS);
    uint4 upz = *reinterpret_cast<const uint4*>(g_p + base + 2 * NPTS);
    uint4 udx = *reinterpret_cast<const uint4*>(g_d + base);
    uint4 udy = *reinterpret_cast<const uint4*>(g_d + base + NPTS);
    uint4 udz = *reinterpret_cast<const uint4*>(g_d + base + 2 * NPTS);

    const float bna = __ldg(&g_bn_a[o]);
    const float bnb = __ldg(&g_bn_b[o]);

    float opx[8], opy[8], opz[8];
    const uint32_t* wpx = &upx.x; const uint32_t* wpy = &upy.x; const uint32_t* wpz = &upz.x;
    const uint32_t* wdx = &udx.x; const uint32_t* wdy = &udy.x; const uint32_t* wdz = &udz.x;
#pragma unroll
    for (int h = 0; h < 4; h++) {
        float2 fpx = __half22float2(*reinterpret_cast<const __half2*>(&wpx[h]));
        float2 fpy = __half22float2(*reinterpret_cast<const __half2*>(&wpy[h]));
        float2 fpz = __half22float2(*reinterpret_cast<const __half2*>(&wpz[h]));
        float2 fdx = __half22float2(*reinterpret_cast<const __half2*>(&wdx[h]));
        float2 fdy = __half22float2(*reinterpret_cast<const __half2*>(&wdy[h]));
        float2 fdz = __half22float2(*reinterpret_cast<const __half2*>(&wdz[h]));
#pragma unroll
        for (int e = 0; e < 2; e++) {
            float ax = e ? fpx.y : fpx.x;
            float ay = e ? fpy.y : fpy.x;
            float az = e ? fpz.y : fpz.x;
            float ex = e ? fdx.y : fdx.x;
            float ey = e ? fdy.y : fdy.x;
            float ez = e ? fdz.y : fdz.x;
            float nrm = sqrtf(ax * ax + ay * ay + az * az);
            float f = bna + bnb / nrm;
            ax *= f; ay *= f; az *= f;
            float dot = ax * ex + ay * ey + az * ez;
            float dsq = ex * ex + ey * ey + ez * ez;
            if (dot < 0.f) {
                float c = 0.8f * dot / (dsq + 1e-6f);
                ax -= c * ex; ay -= c * ey; az -= c * ez;
            }
            int q = h * 2 + e;
            opx[q] = ax; opy[q] = ay; opz[q] = az;
        }
    }
#pragma unroll
    for (int h = 0; h < 2; h++) {
        *reinterpret_cast<float4*>(out + base + h * 4) =
            make_float4(opx[h*4], opx[h*4+1], opx[h*4+2], opx[h*4+3]);
        *reinterpret_cast<float4*>(out + base + NPTS + h * 4) =
            make_float4(opy[h*4], opy[h*4+1], opy[h*4+2], opy[h*4+3]);
        *reinterpret_cast<float4*>(out + base + 2 * NPTS + h * 4) =
            make_float4(opz[h*4], opz[h*4+1], opz[h*4+2], opz[h*4+3]);
    }
}

// ---------------------------------------------------------------------------
extern "C" void kernel_launch(void* const* d_in, const int* in_sizes, int n_in,
                              void* d_out, int out_size)
{
    const float* x     = (const float*)d_in[0];
    const float* Wf    = (const float*)d_in[1];
    const float* Wd    = (const float*)d_in[2];
    const float* gamma = (const float*)d_in[3];
    const float* beta  = (const float*)d_in[4];
    float* out = (float*)d_out;

    (void)cudaFuncSetAttribute(gemm_mma_kernel,
                               cudaFuncAttributeMaxDynamicSharedMemorySize, SMEM_TOTAL);

    convert_w_kernel<<<MTOT, CIN>>>(Wf, Wd);

    dim3 tgrid(LQ / 32, CIN / 64, BQ);
    transpose_split_kernel<<<tgrid, dim3(32, 8)>>>(x);

    zero_stats_kernel<<<1, COUT>>>();          // GEMM stays launch #4 (ncu target)

    dim3 ggrid(MTOT / BM, LQ / BN, BQ);        // (4, 192, 8)
    gemm_mma_kernel<<<ggrid, 256, SMEM_TOTAL>>>();

    stats_kernel<<<dim3(COUT, BQ), 256>>>();
    finalize_kernel<<<1, COUT>>>(gamma, beta);
    epilogue_kernel<<<dim3(NPTS / 2048, COUT, BQ), 256>>>(out);
}